// round 3
// baseline (speedup 1.0000x reference)
#include <cuda_runtime.h>
#include <math.h>

// ---------------- problem constants ----------------
#define NB 4            // batch
#define NC 32           // channels
#define NT 131072       // samples
#define NFR 256         // sig frames
#define SPF 512         // samples per sig frame
#define WS 2048         // window size
#define HOP 1024        // step
#define FR 128          // fft frames per signal
#define KB 1025         // rfft bins
#define BC (NB*NC)      // 128
#define NL 3            // layers
#define ACC_LEN (NT + HOP)   // 132096 overlap-add length

// ---------------- device scratch (static: no runtime allocation) ----------------
__device__ float2 g_tw[WS/2];              // exp(-2*pi*i*t/2048)
__device__ float  g_env[NC*SPF];           // per-channel decay envelope
__device__ float  g_T[NL*NC*KB];           // transfers @ filter_bank
__device__ float  g_x[NL+1][BC*NT];        // layer signals: x0=input, x1..x3 outputs
__device__ float  g_xm[BC*NT];             // channel-mixed signal
__device__ float2 g_spec[BC*FR*KB];        // spectral frames
__device__ float  g_acc[BC*ACC_LEN];       // overlap-add accumulator

// ---------------- init: twiddles + envelopes ----------------
__global__ void init_kernel(const float* __restrict__ decays) {
    int tid = blockIdx.x * blockDim.x + threadIdx.x;
    if (tid < WS/2) {
        float s, c;
        sincospif(-(float)tid * (1.0f/1024.0f), &s, &c);  // angle = -pi*t/1024
        g_tw[tid] = make_float2(c, s);
    }
    if (tid < NC*SPF) {
        int ch = tid / SPF, j = tid - ch*SPF;
        float base = (float)(SPF-1 - j) * (1.0f/(float)(SPF-1));  // linspace(1,0,512)[j], exact 0 at end
        g_env[tid] = powf(base, decays[ch]);
    }
}

// ---------------- T = transfers @ filter_bank (exploit sparsity of transfers) ----------------
__global__ void tmat_kernel(const float* __restrict__ transfers, const float* __restrict__ fb) {
    int lc  = blockIdx.x;              // l*NC + c, 0..95
    int tid = threadIdx.x;             // 256 threads
    const float* tr = transfers + (size_t)lc * KB;
    float acc[5] = {0.f,0.f,0.f,0.f,0.f};
    for (int j = 0; j < KB; j++) {
        float t = tr[j];
        if (t != 0.0f) {               // ~1% nonzero; uniform branch per block
            const float* row = fb + (size_t)j * KB;
            #pragma unroll
            for (int u = 0; u < 5; u++) {
                int k = tid + u*256;
                if (k < KB) acc[u] += t * row[k];
            }
        }
    }
    #pragma unroll
    for (int u = 0; u < 5; u++) {
        int k = tid + u*256;
        if (k < KB) g_T[(size_t)lc*KB + k] = acc[u];
    }
}

// ---------------- excitation: x0 = sig upsampled * envelope * noise ----------------
__global__ void x0_kernel(const float* __restrict__ sig, const float* __restrict__ noise) {
    int idx = blockIdx.x * 256 + threadIdx.x;
    if (idx >= BC*NT) return;
    int bc = idx / NT, t = idx - bc*NT;
    int c = bc & (NC-1);
    int f = t >> 9, j = t & 511;
    g_x[0][idx] = sig[bc*NFR + f] * g_env[c*SPF + j] * noise[t];
}

// ---------------- channel mixing: xm[b,d,t] = sum_c x[b,c,t] * M[c,d] ----------------
__global__ void mix_kernel(int layer, const float* __restrict__ M) {
    __shared__ float xs[NC][256];
    __shared__ float Ms[NC*NC];
    int b = blockIdx.y, t0 = blockIdx.x * 256, tid = threadIdx.x;
    for (int i = tid; i < NC*NC; i += 256) Ms[i] = M[i];
    const float* xin = g_x[layer];
    for (int c = 0; c < NC; c++) xs[c][tid] = xin[(size_t)(b*NC + c)*NT + t0 + tid];
    __syncthreads();
    float xv[NC];
    #pragma unroll
    for (int c = 0; c < NC; c++) xv[c] = xs[c][tid];
    for (int d = 0; d < NC; d++) {
        float s = 0.f;
        #pragma unroll
        for (int c = 0; c < NC; c++) s += xv[c] * Ms[c*NC + d];
        g_xm[(size_t)(b*NC + d)*NT + t0 + tid] = s;
    }
}

// ---------------- zero OA accumulator ----------------
__global__ void zero_acc_kernel() {
    const int n4 = (BC*ACC_LEN) / 4;
    float4* p = (float4*)g_acc;
    for (int i = blockIdx.x*blockDim.x + threadIdx.x; i < n4; i += gridDim.x*blockDim.x)
        p[i] = make_float4(0.f,0.f,0.f,0.f);
}

// ---------------- shared radix-2 FFT core (2048 pts, bit-reversed DIT) ----------------
__device__ __forceinline__ void fft_core(float2* s, const float2* tws, int tid, bool inv) {
    #pragma unroll
    for (int stage = 1; stage <= 11; stage++) {
        int half  = 1 << (stage - 1);
        int tstep = WS >> stage;
        for (int t = tid; t < WS/2; t += 256) {
            int pos = t & (half - 1);
            int i0  = ((t >> (stage - 1)) << stage) | pos;
            float2 w = tws[pos * tstep];
            float wy = inv ? -w.y : w.y;
            float2 u = s[i0], v = s[i0 + half];
            float2 vw = make_float2(v.x*w.x - v.y*wy, v.x*wy + v.y*w.x);
            s[i0]        = make_float2(u.x + vw.x, u.y + vw.y);
            s[i0 + half] = make_float2(u.x - vw.x, u.y - vw.y);
        }
        __syncthreads();
    }
}

// ---------------- forward: window + rfft ----------------
__global__ void __launch_bounds__(256) fwd_fft_kernel() {
    __shared__ float2 s[WS];
    __shared__ float2 tws[WS/2];
    int blk = blockIdx.x;
    int bc = blk >> 7, f = blk & (FR-1);
    int tid = threadIdx.x;
    for (int i = tid; i < WS/2; i += 256) tws[i] = g_tw[i];
    const float* xp = g_xm + (size_t)bc*NT + (size_t)f*HOP;
    for (int i = tid; i < WS; i += 256) {
        int t = f*HOP + i;
        float v = (t < NT) ? xp[i] : 0.0f;             // right-pad by HOP
        float h = 0.5f - 0.5f*cospif((float)i * (1.0f/1024.0f));
        int r = __brev((unsigned)i) >> 21;
        s[r] = make_float2(v * h, 0.0f);
    }
    __syncthreads();
    fft_core(s, tws, tid, false);
    float2* out = g_spec + (size_t)(bc*FR + f)*KB;
    for (int k = tid; k < KB; k += 256) out[k] = s[k];
}

// ---------------- per-(b,c,k) frame recurrence: out_f = (spec_f + out_{f-1}) * T ----------------
__global__ void recur_kernel(int layer) {
    int idx = blockIdx.x * 256 + threadIdx.x;
    if (idx >= BC*KB) return;
    int bc = idx / KB, k = idx - bc*KB;
    int c = bc & (NC-1);
    float T = g_T[(size_t)(layer*NC + c)*KB + k];
    float2 carry = make_float2(0.f, 0.f);
    float2* base = g_spec + (size_t)bc*FR*KB + k;
    #pragma unroll 4
    for (int f = 0; f < FR; f++) {
        float2 v = base[(size_t)f*KB];
        carry.x = (v.x + carry.x) * T;
        carry.y = (v.y + carry.y) * T;
        base[(size_t)f*KB] = carry;
    }
}

// ---------------- inverse: irfft + hann + overlap-add (atomic, exactly 2 adds/addr) ----------------
__global__ void __launch_bounds__(256) inv_fft_kernel() {
    __shared__ float2 s[WS];
    __shared__ float2 tws[WS/2];
    int blk = blockIdx.x;
    int bc = blk >> 7, f = blk & (FR-1);
    int tid = threadIdx.x;
    for (int i = tid; i < WS/2; i += 256) tws[i] = g_tw[i];
    const float2* sp = g_spec + (size_t)(bc*FR + f)*KB;
    for (int i = tid; i < WS; i += 256) {
        float2 v;
        if (i <= WS/2) v = sp[i];
        else { float2 u = sp[WS - i]; v = make_float2(u.x, -u.y); }  // Hermitian extension
        s[__brev((unsigned)i) >> 21] = v;
    }
    __syncthreads();
    fft_core(s, tws, tid, true);
    float* acc = g_acc + (size_t)bc*ACC_LEN + (size_t)f*HOP;
    const float scale = 1.0f / (float)WS;
    for (int i = tid; i < WS; i += 256) {
        float h = 0.5f - 0.5f*cospif((float)i * (1.0f/1024.0f));
        atomicAdd(&acc[i], s[i].x * scale * h);
    }
}

// ---------------- gain + tanh into next layer buffer ----------------
__global__ void tanh_kernel(int layer, const float* __restrict__ gains) {
    int idx = blockIdx.x * 256 + threadIdx.x;
    if (idx >= BC*NT) return;
    int bc = idx / NT, t = idx - bc*NT;
    int c = bc & (NC-1);
    float g = gains[layer*NC + c];
    g_x[layer+1][idx] = tanhf(g_acc[(size_t)bc*ACC_LEN + t] * g);
}

// ---------------- softmax layer mix + channel sum ----------------
__global__ void final_kernel(const float* __restrict__ mixer, float* __restrict__ out) {
    int idx = blockIdx.x * 256 + threadIdx.x;
    if (idx >= NB*NT) return;
    int b = idx / NT, t = idx - b*NT;
    float m0 = mixer[0], m1 = mixer[1], m2 = mixer[2], m3 = mixer[3];
    float mx = fmaxf(fmaxf(m0, m1), fmaxf(m2, m3));
    float e0 = expf(m0-mx), e1 = expf(m1-mx), e2 = expf(m2-mx), e3 = expf(m3-mx);
    float inv = 1.0f / (e0+e1+e2+e3);
    float w0 = e0*inv, w1 = e1*inv, w2 = e2*inv, w3 = e3*inv;
    float acc = 0.f;
    for (int c = 0; c < NC; c++) {
        size_t off = (size_t)(b*NC + c)*NT + t;
        acc += w0*g_x[0][off] + w1*g_x[1][off] + w2*g_x[2][off] + w3*g_x[3][off];
    }
    out[idx] = acc;
}

// ---------------- sig passthrough (second tuple element) ----------------
__global__ void copy_sig_kernel(const float* __restrict__ sig, float* __restrict__ out) {
    int i = blockIdx.x * 256 + threadIdx.x;
    if (i < NB*NC*NFR) out[NB*NT + i] = sig[i];
}

// ---------------- launch ----------------
extern "C" void kernel_launch(void* const* d_in, const int* in_sizes, int n_in,
                              void* d_out, int out_size) {
    const float* sig        = (const float*)d_in[0];   // (B,C,256)
    const float* noise      = (const float*)d_in[1];   // (131072,)
    const float* decays     = (const float*)d_in[2];   // (C,)
    const float* mixer      = (const float*)d_in[3];   // (4,)
    const float* transfers  = (const float*)d_in[4];   // (3,C,1025)
    const float* mixer_mats = (const float*)d_in[5];   // (3,C,C)
    const float* gains      = (const float*)d_in[6];   // (3,C)
    const float* fb         = (const float*)d_in[7];   // (1025,1025)
    float* out = (float*)d_out;

    init_kernel<<<64, 256>>>(decays);                                  // twiddles + env
    tmat_kernel<<<NL*NC, 256>>>(transfers, fb);                        // T matrices
    x0_kernel<<<(BC*NT + 255)/256, 256>>>(sig, noise);                 // excitation

    for (int l = 0; l < NL; l++) {
        dim3 mg(NT/256, NB);
        mix_kernel<<<mg, 256>>>(l, mixer_mats + l*NC*NC);
        zero_acc_kernel<<<1024, 256>>>();
        fwd_fft_kernel<<<BC*FR, 256>>>();
        recur_kernel<<<(BC*KB + 255)/256, 256>>>(l);
        inv_fft_kernel<<<BC*FR, 256>>>();
        tanh_kernel<<<(BC*NT + 255)/256, 256>>>(l, gains);
    }

    final_kernel<<<(NB*NT + 255)/256, 256>>>(mixer, out);
    if (out_size >= NB*NT + NB*NC*NFR)
        copy_sig_kernel<<<(NB*NC*NFR + 255)/256, 256>>>(sig, out);
}

// round 4
// speedup vs baseline: 3.0801x; 3.0801x over previous
#include <cuda_runtime.h>
#include <math.h>

// ---------------- problem constants ----------------
#define NB 4            // batch
#define NC 32           // channels
#define NT 131072       // samples
#define NFR 256         // sig frames
#define SPF 512         // samples per sig frame
#define WS 2048         // window size
#define HOP 1024        // step
#define FR 128          // fft frames per signal
#define KB 1025         // rfft bins
#define BC (NB*NC)      // 128
#define NL 3            // layers
#define ACC_LEN (NT + HOP)   // 132096 overlap-add length
#define NH 1024         // complex FFT length (real 2048 packed)

// skewed smem indexing: conflict-free for stride-4m scatter stores
#define SKW(i) ((i) + ((i) >> 5))
#define SSZ (NH + (NH >> 5) + 1)   // 1057 (covers SKW(1024)=1056)

// ---------------- device scratch (static: no runtime allocation) ----------------
__device__ float  g_env[NC*SPF];           // per-channel decay envelope
__device__ float  g_T[NL*NC*KB];           // transfers @ filter_bank
__device__ float  g_x[NL+1][BC*NT];        // layer signals: x0=input, x1..x3 outputs
__device__ float  g_xm[BC*NT];             // channel-mixed signal
__device__ float2 g_spec[BC*FR*KB];        // spectral frames
__device__ float  g_acc[BC*ACC_LEN];       // overlap-add accumulator

// ---------------- init: envelopes ----------------
__global__ void init_kernel(const float* __restrict__ decays) {
    int tid = blockIdx.x * blockDim.x + threadIdx.x;
    if (tid < NC*SPF) {
        int ch = tid / SPF, j = tid - ch*SPF;
        float base = (float)(SPF-1 - j) * (1.0f/(float)(SPF-1));  // linspace(1,0,512)[j]
        g_env[tid] = powf(base, decays[ch]);
    }
}

// ---------------- T = transfers @ filter_bank (exploit ~1% sparsity) ----------------
__global__ void tmat_kernel(const float* __restrict__ transfers, const float* __restrict__ fb) {
    int lc  = blockIdx.x;              // l*NC + c
    int tid = threadIdx.x;             // 256 threads
    const float* tr = transfers + (size_t)lc * KB;
    float acc[5] = {0.f,0.f,0.f,0.f,0.f};
    for (int j = 0; j < KB; j++) {
        float t = tr[j];
        if (t != 0.0f) {
            const float* row = fb + (size_t)j * KB;
            #pragma unroll
            for (int u = 0; u < 5; u++) {
                int k = tid + u*256;
                if (k < KB) acc[u] += t * row[k];
            }
        }
    }
    #pragma unroll
    for (int u = 0; u < 5; u++) {
        int k = tid + u*256;
        if (k < KB) g_T[(size_t)lc*KB + k] = acc[u];
    }
}

// ---------------- excitation: x0 = sig upsampled * envelope * noise ----------------
__global__ void x0_kernel(const float* __restrict__ sig, const float* __restrict__ noise) {
    int idx = blockIdx.x * 256 + threadIdx.x;
    if (idx >= BC*NT) return;
    int bc = idx / NT, t = idx - bc*NT;
    int c = bc & (NC-1);
    int f = t >> 9, j = t & 511;
    g_x[0][idx] = sig[bc*NFR + f] * g_env[c*SPF + j] * noise[t];
}

// ---------------- channel mixing: xm[b,d,t] = sum_c x[b,c,t] * M[c,d] ----------------
__global__ void mix_kernel(int layer, const float* __restrict__ M) {
    __shared__ float xs[NC][256];
    __shared__ float Ms[NC*NC];
    int b = blockIdx.y, t0 = blockIdx.x * 256, tid = threadIdx.x;
    for (int i = tid; i < NC*NC; i += 256) Ms[i] = M[i];
    const float* xin = g_x[layer];
    for (int c = 0; c < NC; c++) xs[c][tid] = xin[(size_t)(b*NC + c)*NT + t0 + tid];
    __syncthreads();
    float xv[NC];
    #pragma unroll
    for (int c = 0; c < NC; c++) xv[c] = xs[c][tid];
    for (int d = 0; d < NC; d++) {
        float s = 0.f;
        #pragma unroll
        for (int c = 0; c < NC; c++) s += xv[c] * Ms[c*NC + d];
        g_xm[(size_t)(b*NC + d)*NT + t0 + tid] = s;
    }
}

// ---------------- zero OA accumulator ----------------
__global__ void zero_acc_kernel() {
    const int n4 = (BC*ACC_LEN) / 4;
    float4* p = (float4*)g_acc;
    for (int i = blockIdx.x*blockDim.x + threadIdx.x; i < n4; i += gridDim.x*blockDim.x)
        p[i] = make_float4(0.f,0.f,0.f,0.f);
}

// ---------------- radix-4 Stockham core: 1024-pt complex FFT, 256 threads ----------------
// src buffers hold input (natural order); result lands in dst buffers (natural order).
// Twiddle table tw[j] = exp(-2*pi*i*j/1024), j=0..255.
__device__ __forceinline__ void stockham4(float* sR, float* sI, float* dR, float* dI,
                                          const float2* __restrict__ tw, int tid, bool inv) {
    float *srcR = sR, *srcI = sI, *dstR = dR, *dstI = dI;
    #pragma unroll
    for (int s = 0; s < 5; s++) {
        const int m = 1 << (2*s);
        // consecutive loads every stage: t, t+256, t+512, t+768
        float ar = srcR[SKW(tid)],     ai = srcI[SKW(tid)];
        float br = srcR[SKW(tid+256)], bi = srcI[SKW(tid+256)];
        float cr = srcR[SKW(tid+512)], ci = srcI[SKW(tid+512)];
        float dr = srcR[SKW(tid+768)], di = srcI[SKW(tid+768)];
        float apcr = ar+cr, apci = ai+ci, amcr = ar-cr, amci = ai-ci;
        float bpdr = br+dr, bpdi = bi+di, bmdr = br-dr, bmdi = bi-di;
        float t1r, t1i, t3r, t3i;
        if (!inv) { t1r = amcr + bmdi; t1i = amci - bmdr; t3r = amcr - bmdi; t3i = amci + bmdr; }
        else      { t1r = amcr - bmdi; t1i = amci + bmdr; t3r = amcr + bmdi; t3i = amci - bmdr; }
        int j = tid & ~(m-1);             // = p*m < 256
        float2 w = tw[j];
        float w1r = w.x, w1i = inv ? -w.y : w.y;
        float w2r = w1r*w1r - w1i*w1i, w2i = 2.0f*w1r*w1i;
        float w3r = w2r*w1r - w2i*w1i, w3i = w2r*w1i + w2i*w1r;
        int q  = tid & (m-1);
        int ob = q + ((tid >> (2*s)) << (2*s + 2));   // q + 4*m*p
        float s2r = apcr - bpdr, s2i = apci - bpdi;
        dstR[SKW(ob)]      = apcr + bpdr;         dstI[SKW(ob)]      = apci + bpdi;
        dstR[SKW(ob+m)]    = t1r*w1r - t1i*w1i;   dstI[SKW(ob+m)]    = t1r*w1i + t1i*w1r;
        dstR[SKW(ob+2*m)]  = s2r*w2r - s2i*w2i;   dstI[SKW(ob+2*m)]  = s2r*w2i + s2i*w2r;
        dstR[SKW(ob+3*m)]  = t3r*w3r - t3i*w3i;   dstI[SKW(ob+3*m)]  = t3r*w3i + t3i*w3r;
        __syncthreads();
        float* t;
        t = srcR; srcR = dstR; dstR = t;
        t = srcI; srcI = dstI; dstI = t;
    }
    // 5 stages (odd) -> result is in the dR/dI arrays passed by the caller
}

// ---------------- forward: window + real-packed rfft(2048) via cfft(1024) ----------------
__global__ void __launch_bounds__(256) fwd_fft_kernel() {
    __shared__ float r0[SSZ], i0[SSZ], r1[SSZ], i1[SSZ];
    __shared__ float2 tws[256];
    int blk = blockIdx.x;
    int bc = blk >> 7, f = blk & (FR-1);
    int tid = threadIdx.x;
    {
        float sn, cs; sincospif(-(float)tid * (1.0f/512.0f), &sn, &cs);  // -2*pi*tid/1024
        tws[tid] = make_float2(cs, sn);
    }
    const float* xp = g_xm + (size_t)bc*NT + (size_t)f*HOP;
    int tbase = f*HOP;
    for (int i = tid; i < NH; i += 256) {
        int t0 = 2*i;
        float xe = 0.f, xo = 0.f;
        if (tbase + t0 + 1 < NT) { float2 v = ((const float2*)xp)[i]; xe = v.x; xo = v.y; }
        else if (tbase + t0 < NT) { xe = xp[t0]; }
        float he = 0.5f - 0.5f*cospif((float)t0     * (1.0f/1024.0f));
        float ho = 0.5f - 0.5f*cospif((float)(t0+1) * (1.0f/1024.0f));
        r0[SKW(i)] = xe*he;      // z[n] = x_even + i*x_odd (windowed)
        i0[SKW(i)] = xo*ho;
    }
    __syncthreads();
    stockham4(r0, i0, r1, i1, tws, tid, false);   // Z in r1/i1, natural order
    float2* out = g_spec + (size_t)(bc*FR + f)*KB;
    for (int k = tid; k < KB; k += 256) {
        int ka = k & (NH-1);           // k=1024 -> Z[0]
        int kb = (NH - k) & (NH-1);
        float zr = r1[SKW(ka)], zi = i1[SKW(ka)];
        float yr = r1[SKW(kb)], yi = -i1[SKW(kb)];     // Z*[1024-k]
        float er  = 0.5f*(zr+yr), ei  = 0.5f*(zi+yi);
        float orr = 0.5f*(zr-yr), oii = 0.5f*(zi-yi);
        float sn, cs; sincospif(-(float)k * (1.0f/1024.0f), &sn, &cs);  // e^{-i*pi*k/1024}
        float wor = cs*orr - sn*oii, woi = cs*oii + sn*orr;
        out[k] = make_float2(er + woi, ei - wor);      // X = E - i*W*(Z-Z*)/2
    }
}

// ---------------- per-(b,c,k) frame recurrence: out_f = (spec_f + out_{f-1}) * T ----------------
__global__ void recur_kernel(int layer) {
    int idx = blockIdx.x * 256 + threadIdx.x;
    if (idx >= BC*KB) return;
    int bc = idx / KB, k = idx - bc*KB;
    int c = bc & (NC-1);
    float T = g_T[(size_t)(layer*NC + c)*KB + k];
    float2 carry = make_float2(0.f, 0.f);
    float2* base = g_spec + (size_t)bc*FR*KB + k;
    #pragma unroll 4
    for (int f = 0; f < FR; f++) {
        float2 v = base[(size_t)f*KB];
        carry.x = (v.x + carry.x) * T;
        carry.y = (v.y + carry.y) * T;
        base[(size_t)f*KB] = carry;
    }
}

// ---------------- inverse: irfft(2048) via cfft(1024) + hann + overlap-add ----------------
__global__ void __launch_bounds__(256) inv_fft_kernel() {
    __shared__ float r0[SSZ], i0[SSZ], r1[SSZ], i1[SSZ];
    __shared__ float2 tws[256];
    int blk = blockIdx.x;
    int bc = blk >> 7, f = blk & (FR-1);
    int tid = threadIdx.x;
    {
        float sn, cs; sincospif(-(float)tid * (1.0f/512.0f), &sn, &cs);
        tws[tid] = make_float2(cs, sn);
    }
    const float2* sp = g_spec + (size_t)(bc*FR + f)*KB;
    for (int k = tid; k < KB; k += 256) {
        float2 v = sp[k];
        r0[SKW(k)] = v.x; i0[SKW(k)] = v.y;
    }
    __syncthreads();
    // repack: Z[k] = 0.5(X[k]+X*[1024-k]) + 0.5i e^{+i*pi*k/1024}(X[k]-X*[1024-k])
    for (int k = tid; k < NH; k += 256) {
        float xr = r0[SKW(k)], xi = i0[SKW(k)];
        int k2 = NH - k;                               // 1..1024 (k=0 -> X[1024])
        float yr = r0[SKW(k2)], yi = -i0[SKW(k2)];
        float er  = 0.5f*(xr+yr), ei  = 0.5f*(xi+yi);
        float orr = 0.5f*(xr-yr), oii = 0.5f*(xi-yi);
        float sn, cs; sincospif((float)k * (1.0f/1024.0f), &sn, &cs);
        float wor = cs*orr - sn*oii, woi = cs*oii + sn*orr;
        r1[SKW(k)] = er - woi;
        i1[SKW(k)] = ei + wor;
    }
    __syncthreads();
    stockham4(r1, i1, r0, i0, tws, tid, true);        // z in r0/i0 (unnormalized IFFT)
    float* acc = g_acc + (size_t)bc*ACC_LEN + (size_t)f*HOP;
    const float scale = 1.0f/(float)NH;
    for (int n = tid; n < NH; n += 256) {
        int t0 = 2*n;
        float he = 0.5f - 0.5f*cospif((float)t0     * (1.0f/1024.0f));
        float ho = 0.5f - 0.5f*cospif((float)(t0+1) * (1.0f/1024.0f));
        atomicAdd(&acc[t0],   r0[SKW(n)] * scale * he);   // x[2n]   = Re z[n]
        atomicAdd(&acc[t0+1], i0[SKW(n)] * scale * ho);   // x[2n+1] = Im z[n]
    }
}

// ---------------- gain + tanh into next layer buffer ----------------
__global__ void tanh_kernel(int layer, const float* __restrict__ gains) {
    int idx = blockIdx.x * 256 + threadIdx.x;
    if (idx >= BC*NT) return;
    int bc = idx / NT, t = idx - bc*NT;
    int c = bc & (NC-1);
    float g = gains[layer*NC + c];
    g_x[layer+1][idx] = tanhf(g_acc[(size_t)bc*ACC_LEN + t] * g);
}

// ---------------- softmax layer mix + channel sum ----------------
__global__ void final_kernel(const float* __restrict__ mixer, float* __restrict__ out) {
    int idx = blockIdx.x * 256 + threadIdx.x;
    if (idx >= NB*NT) return;
    int b = idx / NT, t = idx - b*NT;
    float m0 = mixer[0], m1 = mixer[1], m2 = mixer[2], m3 = mixer[3];
    float mx = fmaxf(fmaxf(m0, m1), fmaxf(m2, m3));
    float e0 = expf(m0-mx), e1 = expf(m1-mx), e2 = expf(m2-mx), e3 = expf(m3-mx);
    float inv = 1.0f / (e0+e1+e2+e3);
    float w0 = e0*inv, w1 = e1*inv, w2 = e2*inv, w3 = e3*inv;
    float acc = 0.f;
    for (int c = 0; c < NC; c++) {
        size_t off = (size_t)(b*NC + c)*NT + t;
        acc += w0*g_x[0][off] + w1*g_x[1][off] + w2*g_x[2][off] + w3*g_x[3][off];
    }
    out[idx] = acc;
}

// ---------------- sig passthrough (second tuple element) ----------------
__global__ void copy_sig_kernel(const float* __restrict__ sig, float* __restrict__ out) {
    int i = blockIdx.x * 256 + threadIdx.x;
    if (i < NB*NC*NFR) out[NB*NT + i] = sig[i];
}

// ---------------- launch ----------------
extern "C" void kernel_launch(void* const* d_in, const int* in_sizes, int n_in,
                              void* d_out, int out_size) {
    const float* sig        = (const float*)d_in[0];   // (B,C,256)
    const float* noise      = (const float*)d_in[1];   // (131072,)
    const float* decays     = (const float*)d_in[2];   // (C,)
    const float* mixer      = (const float*)d_in[3];   // (4,)
    const float* transfers  = (const float*)d_in[4];   // (3,C,1025)
    const float* mixer_mats = (const float*)d_in[5];   // (3,C,C)
    const float* gains      = (const float*)d_in[6];   // (3,C)
    const float* fb         = (const float*)d_in[7];   // (1025,1025)
    float* out = (float*)d_out;

    init_kernel<<<64, 256>>>(decays);
    tmat_kernel<<<NL*NC, 256>>>(transfers, fb);
    x0_kernel<<<(BC*NT + 255)/256, 256>>>(sig, noise);

    for (int l = 0; l < NL; l++) {
        dim3 mg(NT/256, NB);
        mix_kernel<<<mg, 256>>>(l, mixer_mats + l*NC*NC);
        zero_acc_kernel<<<1024, 256>>>();
        fwd_fft_kernel<<<BC*FR, 256>>>();
        recur_kernel<<<(BC*KB + 255)/256, 256>>>(l);
        inv_fft_kernel<<<BC*FR, 256>>>();
        tanh_kernel<<<(BC*NT + 255)/256, 256>>>(l, gains);
    }

    final_kernel<<<(NB*NT + 255)/256, 256>>>(mixer, out);
    if (out_size >= NB*NT + NB*NC*NFR)
        copy_sig_kernel<<<(NB*NC*NFR + 255)/256, 256>>>(sig, out);
}

// round 7
// speedup vs baseline: 3.4615x; 1.1238x over previous
#include <cuda_runtime.h>
#include <math.h>

// ---------------- problem constants ----------------
#define NB 4            // batch
#define NC 32           // channels
#define NT 131072       // samples
#define NFR 256         // sig frames
#define SPF 512         // samples per sig frame
#define WS 2048         // window size
#define HOP 1024        // step
#define FR 128          // fft frames per signal
#define KB 1025         // rfft bins
#define BC (NB*NC)      // 128
#define NL 3            // layers
#define NH 1024         // complex FFT length (real 2048 packed)

// skewed smem indexing: conflict-free for stride-4m scatter stores
#define SKW(i) ((i) + ((i) >> 5))
#define SSZ (NH + (NH >> 5) + 1)   // 1057

// dynamic smem layout (floats):
//   float2: spec[2][KB], carry[KB], tw2[KB], tws[256]   = 4356 float2
//   float : 8 FFT buffers [SSZ], Trow[KB], hann[2048], tail[1024]
#define SMEM_FLOATS (2*(2*KB + KB + KB + 256) + 8*SSZ + KB + 2048 + 1024)
#define SMEM_BYTES (SMEM_FLOATS * 4)

// ---------------- device scratch (static: no runtime allocation) ----------------
__device__ float  g_env[NC*SPF];           // per-channel decay envelope
__device__ float  g_T[NL*NC*KB];           // transfers @ filter_bank
__device__ float  g_x[NL+1][BC*NT];        // layer signals: x0=input, x1..x3 outputs
__device__ float  g_xm[BC*NT];             // channel-mixed signal

// ---------------- init: envelopes ----------------
__global__ void init_kernel(const float* __restrict__ decays) {
    int tid = blockIdx.x * blockDim.x + threadIdx.x;
    if (tid < NC*SPF) {
        int ch = tid / SPF, j = tid - ch*SPF;
        float base = (float)(SPF-1 - j) * (1.0f/(float)(SPF-1));
        g_env[tid] = powf(base, decays[ch]);
    }
}

// ---------------- T = transfers @ filter_bank (exploit ~1% sparsity) ----------------
__global__ void tmat_kernel(const float* __restrict__ transfers, const float* __restrict__ fb) {
    int lc  = blockIdx.x;
    int tid = threadIdx.x;
    const float* tr = transfers + (size_t)lc * KB;
    float acc[5] = {0.f,0.f,0.f,0.f,0.f};
    for (int j = 0; j < KB; j++) {
        float t = tr[j];
        if (t != 0.0f) {
            const float* row = fb + (size_t)j * KB;
            #pragma unroll
            for (int u = 0; u < 5; u++) {
                int k = tid + u*256;
                if (k < KB) acc[u] += t * row[k];
            }
        }
    }
    #pragma unroll
    for (int u = 0; u < 5; u++) {
        int k = tid + u*256;
        if (k < KB) g_T[(size_t)lc*KB + k] = acc[u];
    }
}

// ---------------- excitation: x0 = sig upsampled * envelope * noise ----------------
__global__ void x0_kernel(const float* __restrict__ sig, const float* __restrict__ noise) {
    int idx = blockIdx.x * 256 + threadIdx.x;
    if (idx >= BC*NT) return;
    int bc = idx / NT, t = idx - bc*NT;
    int c = bc & (NC-1);
    int f = t >> 9, j = t & 511;
    g_x[0][idx] = sig[bc*NFR + f] * g_env[c*SPF + j] * noise[t];
}

// ---------------- channel mixing (pure-register, DRAM-bound) ----------------
__global__ void __launch_bounds__(256) mix_kernel(int layer, const float* __restrict__ M) {
    __shared__ float Ms[NC*NC];
    int b = blockIdx.y, t = blockIdx.x * 256 + threadIdx.x;
    for (int i = threadIdx.x; i < NC*NC; i += 256) Ms[i] = M[i];
    __syncthreads();
    const float* xin = g_x[layer] + (size_t)b*NC*NT + t;
    float xv[NC];
    #pragma unroll
    for (int c = 0; c < NC; c++) xv[c] = xin[(size_t)c*NT];
    float* xo = g_xm + (size_t)b*NC*NT + t;
    #pragma unroll
    for (int d = 0; d < NC; d++) {
        float s = 0.f;
        #pragma unroll
        for (int c = 0; c < NC; c++) s += xv[c] * Ms[c*NC + d];
        xo[(size_t)d*NT] = s;
    }
}

// ---------------- half-block named barrier ----------------
__device__ __forceinline__ void barh(int id) {
    asm volatile("bar.sync %0, 256;" :: "r"(id) : "memory");
}

// ---------------- radix-4 Stockham core: 1024-pt complex FFT, 256 threads of one half ----------------
__device__ __forceinline__ void stockham4(float* sR, float* sI, float* dR, float* dI,
                                          const float2* tw, int lt, bool inv, int barid) {
    float *srcR = sR, *srcI = sI, *dstR = dR, *dstI = dI;
    #pragma unroll
    for (int s = 0; s < 5; s++) {
        const int m = 1 << (2*s);
        float ar = srcR[SKW(lt)],     ai = srcI[SKW(lt)];
        float br = srcR[SKW(lt+256)], bi = srcI[SKW(lt+256)];
        float cr = srcR[SKW(lt+512)], ci = srcI[SKW(lt+512)];
        float dr = srcR[SKW(lt+768)], di = srcI[SKW(lt+768)];
        float apcr = ar+cr, apci = ai+ci, amcr = ar-cr, amci = ai-ci;
        float bpdr = br+dr, bpdi = bi+di, bmdr = br-dr, bmdi = bi-di;
        float t1r, t1i, t3r, t3i;
        if (!inv) { t1r = amcr + bmdi; t1i = amci - bmdr; t3r = amcr - bmdi; t3i = amci + bmdr; }
        else      { t1r = amcr - bmdi; t1i = amci + bmdr; t3r = amcr + bmdi; t3i = amci - bmdr; }
        int j = lt & ~(m-1);
        float2 w = tw[j];
        float w1r = w.x, w1i = inv ? -w.y : w.y;
        float w2r = w1r*w1r - w1i*w1i, w2i = 2.0f*w1r*w1i;
        float w3r = w2r*w1r - w2i*w1i, w3i = w2r*w1i + w2i*w1r;
        int q  = lt & (m-1);
        int ob = q + ((lt >> (2*s)) << (2*s + 2));
        float s2r = apcr - bpdr, s2i = apci - bpdi;
        dstR[SKW(ob)]      = apcr + bpdr;         dstI[SKW(ob)]      = apci + bpdi;
        dstR[SKW(ob+m)]    = t1r*w1r - t1i*w1i;   dstI[SKW(ob+m)]    = t1r*w1i + t1i*w1r;
        dstR[SKW(ob+2*m)]  = s2r*w2r - s2i*w2i;   dstI[SKW(ob+2*m)]  = s2r*w2i + s2i*w2r;
        dstR[SKW(ob+3*m)]  = t3r*w3r - t3i*w3i;   dstI[SKW(ob+3*m)]  = t3r*w3i + t3i*w3r;
        barh(barid);
        float* t;
        t = srcR; srcR = dstR; dstR = t;
        t = srcI; srcI = dstI; dstI = t;
    }
    // result in dR/dI (5 stages = odd number of swaps)
}

// ---------------- fused per-(b,c) layer kernel ----------------
// Warps 0-7 (producer): window + fwd rfft of frame f into spec ping-pong.
// Warps 8-15 (consumer): recurrence + irfft + hann + overlap-add + gain*tanh of frame f-1.
__global__ void __launch_bounds__(512) layer_kernel(int layer, const float* __restrict__ gains) {
    extern __shared__ float sm[];
    float2* spec  = (float2*)sm;                 // [2][KB] ping-pong
    float2* carry = spec + 2*KB;                 // [KB]
    float2* tw2   = carry + KB;                  // [KB]  e^{-i*pi*k/1024}
    float2* tws   = tw2 + KB;                    // [256] e^{-2*pi*i*j/1024}
    float*  fbuf  = (float*)(tws + 256);
    float* pR0 = fbuf;            float* pI0 = fbuf + SSZ;
    float* pR1 = fbuf + 2*SSZ;    float* pI1 = fbuf + 3*SSZ;
    float* cR0 = fbuf + 4*SSZ;    float* cI0 = fbuf + 5*SSZ;
    float* cR1 = fbuf + 6*SSZ;    float* cI1 = fbuf + 7*SSZ;
    float* Trow = fbuf + 8*SSZ;                  // [KB]
    float* hann = Trow + KB;                     // [2048]
    float* tail = hann + 2048;                   // [1024]

    int tid = threadIdx.x;
    int bc  = blockIdx.x;
    int c   = bc & (NC-1);
    int half = tid >> 8;         // 0 = producer, 1 = consumer
    int lt   = tid & 255;
    float gain = gains[layer*NC + c];

    // one-time tables
    for (int j = tid; j < 256; j += 512) {
        float sn, cs; sincospif(-(float)j * (1.0f/512.0f), &sn, &cs);
        tws[j] = make_float2(cs, sn);
    }
    for (int k = tid; k < KB; k += 512) {
        float sn, cs; sincospif(-(float)k * (1.0f/1024.0f), &sn, &cs);
        tw2[k] = make_float2(cs, sn);
        carry[k] = make_float2(0.f, 0.f);
        Trow[k] = g_T[(size_t)(layer*NC + c)*KB + k];
    }
    for (int i = tid; i < 2048; i += 512)
        hann[i] = 0.5f - 0.5f*cospif((float)i * (1.0f/1024.0f));
    for (int i = tid; i < 1024; i += 512) tail[i] = 0.f;
    __syncthreads();

    const float2* xin2 = (const float2*)(g_xm + (size_t)bc*NT);
    float* xout = g_x[layer+1] + (size_t)bc*NT;
    const float scale = 1.0f/(float)NH;

    for (int f = 0; f <= FR; f++) {
        if (half == 0 && f < FR) {
            // ---- producer: window + pack + fwd FFT + Hermitian unpack ----
            int ibase = f * (HOP/2);       // float2 index of frame start
            for (int i = lt; i < NH; i += 256) {
                int gi = ibase + i;
                float2 v = (gi < NT/2) ? xin2[gi] : make_float2(0.f, 0.f);
                pR0[SKW(i)] = v.x * hann[2*i];
                pI0[SKW(i)] = v.y * hann[2*i+1];
            }
            barh(1);
            stockham4(pR0, pI0, pR1, pI1, tws, lt, false, 1);  // result pR1/pI1
            float2* out = spec + (f & 1)*KB;
            for (int k = lt; k < KB; k += 256) {
                int ka = k & (NH-1), kb = (NH - k) & (NH-1);
                float zr = pR1[SKW(ka)], zi = pI1[SKW(ka)];
                float yr = pR1[SKW(kb)], yi = -pI1[SKW(kb)];
                float er  = 0.5f*(zr+yr), ei  = 0.5f*(zi+yi);
                float orr = 0.5f*(zr-yr), oii = 0.5f*(zi-yi);
                float cs = tw2[k].x, sn = tw2[k].y;        // e^{-i*pi*k/1024}
                float wor = cs*orr - sn*oii, woi = cs*oii + sn*orr;
                out[k] = make_float2(er + woi, ei - wor);
            }
        }
        if (half == 1 && f >= 1) {
            // ---- consumer: recurrence + repack + inv FFT + OA + tanh ----
            int fc = f - 1;
            const float2* sp = spec + (fc & 1)*KB;
            for (int k = lt; k < KB; k += 256) {
                float2 v = sp[k]; float2 cr = carry[k]; float T = Trow[k];
                cr.x = (v.x + cr.x) * T;
                cr.y = (v.y + cr.y) * T;
                carry[k] = cr;
            }
            barh(2);
            // repack X -> Z for 1024-pt inverse
            for (int k = lt; k < NH; k += 256) {
                float2 X = carry[k];
                float2 Yc = carry[NH - k];
                float yr = Yc.x, yi = -Yc.y;
                float er  = 0.5f*(X.x+yr), ei  = 0.5f*(X.y+yi);
                float orr = 0.5f*(X.x-yr), oii = 0.5f*(X.y-yi);
                float cs = tw2[k].x, sn = -tw2[k].y;       // e^{+i*pi*k/1024}
                float wor = cs*orr - sn*oii, woi = cs*oii + sn*orr;
                cR1[SKW(k)] = er - woi;
                cI1[SKW(k)] = ei + wor;
            }
            barh(2);
            stockham4(cR1, cI1, cR0, cI0, tws, lt, true, 2);  // result cR0/cI0
            // window + OA (two-phase via tail)
            float vals[8];
            #pragma unroll
            for (int u = 0; u < 4; u++) {
                int n = lt + u*256;
                vals[2*u]   = cR0[SKW(n)] * scale * hann[2*n];
                vals[2*u+1] = cI0[SKW(n)] * scale * hann[2*n+1];
            }
            float2* op = (float2*)(xout + (size_t)fc*HOP);
            #pragma unroll
            for (int u = 0; u < 2; u++) {      // n < 512: first half + old tail -> output
                int n = lt + u*256;
                float s0 = tail[2*n]   + vals[2*u];
                float s1 = tail[2*n+1] + vals[2*u+1];
                op[n] = make_float2(tanhf(gain*s0), tanhf(gain*s1));
            }
            barh(2);
            #pragma unroll
            for (int u = 2; u < 4; u++) {      // n >= 512: second half -> new tail
                int n = lt + u*256;
                int j = 2*(n - 512);
                tail[j]   = vals[2*u];
                tail[j+1] = vals[2*u+1];
            }
        }
        __syncthreads();   // frame handoff: spec ping-pong becomes visible
    }
}

// ---------------- softmax layer mix + channel sum ----------------
__global__ void final_kernel(const float* __restrict__ mixer, float* __restrict__ out) {
    int idx = blockIdx.x * 256 + threadIdx.x;
    if (idx >= NB*NT) return;
    int b = idx / NT, t = idx - b*NT;
    float m0 = mixer[0], m1 = mixer[1], m2 = mixer[2], m3 = mixer[3];
    float mx = fmaxf(fmaxf(m0, m1), fmaxf(m2, m3));
    float e0 = expf(m0-mx), e1 = expf(m1-mx), e2 = expf(m2-mx), e3 = expf(m3-mx);
    float inv = 1.0f / (e0+e1+e2+e3);
    float w0 = e0*inv, w1 = e1*inv, w2 = e2*inv, w3 = e3*inv;
    float acc = 0.f;
    for (int c = 0; c < NC; c++) {
        size_t off = (size_t)(b*NC + c)*NT + t;
        acc += w0*g_x[0][off] + w1*g_x[1][off] + w2*g_x[2][off] + w3*g_x[3][off];
    }
    out[idx] = acc;
}

// ---------------- sig passthrough ----------------
__global__ void copy_sig_kernel(const float* __restrict__ sig, float* __restrict__ out) {
    int i = blockIdx.x * 256 + threadIdx.x;
    if (i < NB*NC*NFR) out[NB*NT + i] = sig[i];
}

// ---------------- launch ----------------
extern "C" void kernel_launch(void* const* d_in, const int* in_sizes, int n_in,
                              void* d_out, int out_size) {
    const float* sig        = (const float*)d_in[0];
    const float* noise      = (const float*)d_in[1];
    const float* decays     = (const float*)d_in[2];
    const float* mixer      = (const float*)d_in[3];
    const float* transfers  = (const float*)d_in[4];
    const float* mixer_mats = (const float*)d_in[5];
    const float* gains      = (const float*)d_in[6];
    const float* fb         = (const float*)d_in[7];
    float* out = (float*)d_out;

    cudaFuncSetAttribute(layer_kernel, cudaFuncAttributeMaxDynamicSharedMemorySize, SMEM_BYTES);

    init_kernel<<<64, 256>>>(decays);
    tmat_kernel<<<NL*NC, 256>>>(transfers, fb);
    x0_kernel<<<(BC*NT + 255)/256, 256>>>(sig, noise);

    for (int l = 0; l < NL; l++) {
        dim3 mg(NT/256, NB);
        mix_kernel<<<mg, 256>>>(l, mixer_mats + l*NC*NC);
        layer_kernel<<<BC, 512, SMEM_BYTES>>>(l, gains);
    }

    final_kernel<<<(NB*NT + 255)/256, 256>>>(mixer, out);
    if (out_size >= NB*NT + NB*NC*NFR)
        copy_sig_kernel<<<(NB*NC*NFR + 255)/256, 256>>>(sig, out);
}

// round 8
// speedup vs baseline: 4.1973x; 1.2126x over previous
#include <cuda_runtime.h>
#include <math.h>

// ---------------- problem constants ----------------
#define NB 4            // batch
#define NC 32           // channels
#define NT 131072       // samples
#define NFR 256         // sig frames
#define SPF 512         // samples per sig frame
#define WS 2048         // window size
#define HOP 1024        // step
#define FR 128          // fft frames per signal
#define KB 1025         // rfft bins
#define BC (NB*NC)      // 128
#define NL 3            // layers
#define NH 1024         // complex FFT length (real 2048 packed)

// skewed smem indexing: conflict-free for stride-4m scatter stores
#define SKW(i) ((i) + ((i) >> 5))
#define SSZ (NH + (NH >> 5) + 1)   // 1057

// cons kernel dynamic smem (floats):
//  float2: specsm[2][KB], carry[KB], tw2[KB], tws[256]
//  float : 4 FFT buffers [SSZ], Trow[KB], hann[2048], tail[2][1024]
#define CONS_FLOATS (2*(2*KB + KB + KB + 256) + 4*SSZ + KB + 2048 + 2048)
#define CONS_BYTES (CONS_FLOATS * 4)

// ---------------- device scratch (static: no runtime allocation) ----------------
__device__ float  g_env[NC*SPF];
__device__ float  g_T[NL*NC*KB];
__device__ float  g_x[NL+1][BC*NT];
__device__ float  g_xm[BC*NT];
__device__ float2 g_spec[BC*FR*KB];
__device__ int    g_ident[NL];

// ---------------- init: envelopes ----------------
__global__ void init_kernel(const float* __restrict__ decays) {
    int tid = blockIdx.x * blockDim.x + threadIdx.x;
    if (tid < NC*SPF) {
        int ch = tid / SPF, j = tid - ch*SPF;
        float base = (float)(SPF-1 - j) * (1.0f/(float)(SPF-1));
        g_env[tid] = powf(base, decays[ch]);
    }
}

// ---------------- identity check for mixer matrices ----------------
__global__ void ident_kernel(const float* __restrict__ M) {
    __shared__ int ok;
    if (threadIdx.x == 0) ok = 1;
    __syncthreads();
    const float* m = M + blockIdx.x * NC*NC;
    for (int i = threadIdx.x; i < NC*NC; i += 256) {
        float expect = ((i / NC) == (i % NC)) ? 1.0f : 0.0f;
        if (m[i] != expect) atomicExch(&ok, 0);
    }
    __syncthreads();
    if (threadIdx.x == 0) g_ident[blockIdx.x] = ok;
}

// ---------------- T = transfers @ filter_bank (exploit ~1% sparsity) ----------------
__global__ void tmat_kernel(const float* __restrict__ transfers, const float* __restrict__ fb) {
    int lc  = blockIdx.x;
    int tid = threadIdx.x;
    const float* tr = transfers + (size_t)lc * KB;
    float acc[5] = {0.f,0.f,0.f,0.f,0.f};
    for (int j = 0; j < KB; j++) {
        float t = tr[j];
        if (t != 0.0f) {
            const float* row = fb + (size_t)j * KB;
            #pragma unroll
            for (int u = 0; u < 5; u++) {
                int k = tid + u*256;
                if (k < KB) acc[u] += t * row[k];
            }
        }
    }
    #pragma unroll
    for (int u = 0; u < 5; u++) {
        int k = tid + u*256;
        if (k < KB) g_T[(size_t)lc*KB + k] = acc[u];
    }
}

// ---------------- excitation ----------------
__global__ void x0_kernel(const float* __restrict__ sig, const float* __restrict__ noise) {
    int idx = blockIdx.x * 256 + threadIdx.x;
    if (idx >= BC*NT) return;
    int bc = idx / NT, t = idx - bc*NT;
    int c = bc & (NC-1);
    int f = t >> 9, j = t & 511;
    g_x[0][idx] = sig[bc*NFR + f] * g_env[c*SPF + j] * noise[t];
}

// ---------------- channel mixing (only runs when mixer_mat != identity) ----------------
__global__ void __launch_bounds__(256) mix_kernel(int layer, const float* __restrict__ M) {
    if (g_ident[layer]) return;
    __shared__ float Ms[NC*NC];
    int b = blockIdx.y, t = blockIdx.x * 256 + threadIdx.x;
    for (int i = threadIdx.x; i < NC*NC; i += 256) Ms[i] = M[i];
    __syncthreads();
    const float* xin = g_x[layer] + (size_t)b*NC*NT + t;
    float xv[NC];
    #pragma unroll
    for (int c = 0; c < NC; c++) xv[c] = xin[(size_t)c*NT];
    float* xo = g_xm + (size_t)b*NC*NT + t;
    #pragma unroll
    for (int d = 0; d < NC; d++) {
        float s = 0.f;
        #pragma unroll
        for (int c = 0; c < NC; c++) s += xv[c] * Ms[c*NC + d];
        xo[(size_t)d*NT] = s;
    }
}

// ---------------- barrier select: 0 = __syncthreads (256-thread block), 1 = named half-barrier ----------------
__device__ __forceinline__ void sync_sel(int named) {
    if (named) asm volatile("bar.sync 1, 256;" ::: "memory");
    else __syncthreads();
}

// ---------------- Stockham stages 1..4 (radix-4, 1024 pts, 256 threads); src=A, result lands in A ----------------
__device__ __forceinline__ void stages14(float* AR, float* AI, float* BR, float* BI,
                                         const float2* tws, int lt, bool inv, int named) {
    float *sR = AR, *sI = AI, *dR = BR, *dI = BI;
    #pragma unroll
    for (int s = 1; s < 5; s++) {
        const int m = 1 << (2*s);
        float ar = sR[SKW(lt)],     ai = sI[SKW(lt)];
        float br = sR[SKW(lt+256)], bi = sI[SKW(lt+256)];
        float cr = sR[SKW(lt+512)], ci = sI[SKW(lt+512)];
        float dr = sR[SKW(lt+768)], di = sI[SKW(lt+768)];
        float apcr = ar+cr, apci = ai+ci, amcr = ar-cr, amci = ai-ci;
        float bpdr = br+dr, bpdi = bi+di, bmdr = br-dr, bmdi = bi-di;
        float t1r, t1i, t3r, t3i;
        if (!inv) { t1r = amcr + bmdi; t1i = amci - bmdr; t3r = amcr - bmdi; t3i = amci + bmdr; }
        else      { t1r = amcr - bmdi; t1i = amci + bmdr; t3r = amcr + bmdi; t3i = amci - bmdr; }
        int j = lt & ~(m-1);
        float2 w = tws[j];
        float w1r = w.x, w1i = inv ? -w.y : w.y;
        float w2r = w1r*w1r - w1i*w1i, w2i = 2.0f*w1r*w1i;
        float w3r = w2r*w1r - w2i*w1i, w3i = w2r*w1i + w2i*w1r;
        int q  = lt & (m-1);
        int ob = q + ((lt >> (2*s)) << (2*s + 2));
        float s2r = apcr - bpdr, s2i = apci - bpdi;
        dR[SKW(ob)]      = apcr + bpdr;         dI[SKW(ob)]      = apci + bpdi;
        dR[SKW(ob+m)]    = t1r*w1r - t1i*w1i;   dI[SKW(ob+m)]    = t1r*w1i + t1i*w1r;
        dR[SKW(ob+2*m)]  = s2r*w2r - s2i*w2i;   dI[SKW(ob+2*m)]  = s2r*w2i + s2i*w2r;
        dR[SKW(ob+3*m)]  = t3r*w3r - t3i*w3i;   dI[SKW(ob+3*m)]  = t3r*w3i + t3i*w3r;
        sync_sel(named);
        float* t;
        t = sR; sR = dR; dR = t;
        t = sI; sI = dI; dI = t;
    }
    // 4 stages = even swaps -> result back in AR/AI
}

// ---------------- stage 0 from registers (m=1): z[lt + u*256] -> buf[4*lt + u] ----------------
__device__ __forceinline__ void stage0_reg(const float* zr, const float* zi,
                                           float* AR, float* AI,
                                           const float2* tws, int lt, bool inv) {
    float apcr = zr[0]+zr[2], apci = zi[0]+zi[2], amcr = zr[0]-zr[2], amci = zi[0]-zi[2];
    float bpdr = zr[1]+zr[3], bpdi = zi[1]+zi[3], bmdr = zr[1]-zr[3], bmdi = zi[1]-zi[3];
    float t1r, t1i, t3r, t3i;
    if (!inv) { t1r = amcr + bmdi; t1i = amci - bmdr; t3r = amcr - bmdi; t3i = amci + bmdr; }
    else      { t1r = amcr - bmdi; t1i = amci + bmdr; t3r = amcr + bmdi; t3i = amci - bmdr; }
    float2 w = tws[lt];
    float w1r = w.x, w1i = inv ? -w.y : w.y;
    float w2r = w1r*w1r - w1i*w1i, w2i = 2.0f*w1r*w1i;
    float w3r = w2r*w1r - w2i*w1i, w3i = w2r*w1i + w2i*w1r;
    float s2r = apcr - bpdr, s2i = apci - bpdi;
    int ob = 4*lt;
    AR[SKW(ob)]   = apcr + bpdr;         AI[SKW(ob)]   = apci + bpdi;
    AR[SKW(ob+1)] = t1r*w1r - t1i*w1i;   AI[SKW(ob+1)] = t1r*w1i + t1i*w1r;
    AR[SKW(ob+2)] = s2r*w2r - s2i*w2i;   AI[SKW(ob+2)] = s2r*w2i + s2i*w2r;
    AR[SKW(ob+3)] = t3r*w3r - t3i*w3i;   AI[SKW(ob+3)] = t3r*w3i + t3i*w3r;
}

// ---------------- forward FFT: one frame per block, window + stage0 fused from global ----------------
__global__ void __launch_bounds__(256) fwd_kernel(int layer) {
    __shared__ float AR[SSZ], AI[SSZ], BR[SSZ], BI[SSZ];
    __shared__ float2 tws[256];
    int blk = blockIdx.x, bc = blk >> 7, f = blk & (FR-1), tid = threadIdx.x;
    { float sn, cs; sincospif(-(float)tid * (1.0f/512.0f), &sn, &cs); tws[tid] = make_float2(cs, sn); }
    const float* src = g_ident[layer] ? g_x[layer] : g_xm;
    const float2* xin2 = (const float2*)(src + (size_t)bc*NT);
    int ibase = f * (HOP/2);
    float zr[4], zi[4];
    #pragma unroll
    for (int u = 0; u < 4; u++) {
        int n = tid + u*256, gi = ibase + n;
        float2 v = (gi < NT/2) ? xin2[gi] : make_float2(0.f, 0.f);
        float he = 0.5f - 0.5f*cospif((float)n * (1.0f/512.0f));            // hann[2n]
        float ho = 0.5f - 0.5f*cospif((float)(2*n+1) * (1.0f/1024.0f));     // hann[2n+1]
        zr[u] = v.x * he;
        zi[u] = v.y * ho;
    }
    stage0_reg(zr, zi, AR, AI, tws, tid, false);
    __syncthreads();
    stages14(AR, AI, BR, BI, tws, tid, false, 0);      // result in AR/AI
    float2* out = g_spec + (size_t)(bc*FR + f)*KB;
    for (int k = tid; k < KB; k += 256) {
        int ka = k & (NH-1), kb = (NH - k) & (NH-1);
        float xr = AR[SKW(ka)], xi = AI[SKW(ka)];
        float yr = AR[SKW(kb)], yi = -AI[SKW(kb)];
        float er  = 0.5f*(xr+yr), ei  = 0.5f*(xi+yi);
        float orr = 0.5f*(xr-yr), oii = 0.5f*(xi-yi);
        float sn, cs; sincospif(-(float)k * (1.0f/1024.0f), &sn, &cs);
        float wor = cs*orr - sn*oii, woi = cs*oii + sn*orr;
        out[k] = make_float2(er + woi, ei - wor);
    }
}

// ---------------- consumer: recurrence + irfft + OA + tanh; per (b,c), spec prefetched by half 1 ----------------
__global__ void __launch_bounds__(512) cons_kernel(int layer, const float* __restrict__ gains) {
    extern __shared__ float sm[];
    float2* specsm = (float2*)sm;          // [2][KB]
    float2* carry  = specsm + 2*KB;        // [KB]
    float2* tw2    = carry + KB;           // [KB]  e^{-i*pi*k/1024}
    float2* tws    = tw2 + KB;             // [256]
    float*  fbuf   = (float*)(tws + 256);
    float* AR = fbuf;           float* AI = fbuf + SSZ;
    float* BR = fbuf + 2*SSZ;   float* BI = fbuf + 3*SSZ;
    float* Trow = fbuf + 4*SSZ;            // [KB]
    float* hann = Trow + KB;               // [2048]
    float* tail = hann + 2048;             // [2][1024]

    int tid = threadIdx.x;
    int bc  = blockIdx.x;
    int c   = bc & (NC-1);
    int half = tid >> 8;
    int lt   = tid & 255;
    float gain = gains[layer*NC + c];

    for (int j = tid; j < 256; j += 512) {
        float sn, cs; sincospif(-(float)j * (1.0f/512.0f), &sn, &cs);
        tws[j] = make_float2(cs, sn);
    }
    for (int k = tid; k < KB; k += 512) {
        float sn, cs; sincospif(-(float)k * (1.0f/1024.0f), &sn, &cs);
        tw2[k] = make_float2(cs, sn);
        carry[k] = make_float2(0.f, 0.f);
        Trow[k] = g_T[(size_t)(layer*NC + c)*KB + k];
    }
    for (int i = tid; i < 2048; i += 512)
        hann[i] = 0.5f - 0.5f*cospif((float)i * (1.0f/1024.0f));
    for (int i = tid; i < 2048; i += 512) tail[i] = 0.f;

    const float2* specg = g_spec + (size_t)bc*FR*KB;
    float* xout = g_x[layer+1] + (size_t)bc*NT;
    const float scale = 1.0f/(float)NH;

    // prefetch frame 0
    if (half == 1) {
        #pragma unroll
        for (int u = 0; u < 5; u++) {
            int k = lt + u*256;
            if (k < KB) specsm[k] = specg[k];
        }
    }
    __syncthreads();

    for (int f = 0; f < FR; f++) {
        if (half == 0) {
            const float2* spf = specsm + (f & 1)*KB;
            // recurrence
            #pragma unroll
            for (int u = 0; u < 5; u++) {
                int k = lt + u*256;
                if (k < KB) {
                    float2 v = spf[k]; float2 cr = carry[k]; float T = Trow[k];
                    cr.x = (v.x + cr.x) * T;
                    cr.y = (v.y + cr.y) * T;
                    carry[k] = cr;
                }
            }
            sync_sel(1);
            // repack X->Z fused with inverse stage 0
            float zr[4], zi[4];
            #pragma unroll
            for (int u = 0; u < 4; u++) {
                int k = lt + u*256;
                float2 X = carry[k];
                float2 Yc = carry[NH - k];
                float yr = Yc.x, yi = -Yc.y;
                float er  = 0.5f*(X.x+yr), ei  = 0.5f*(X.y+yi);
                float orr = 0.5f*(X.x-yr), oii = 0.5f*(X.y-yi);
                float cs = tw2[k].x, sn = -tw2[k].y;   // e^{+i*pi*k/1024}
                float wor = cs*orr - sn*oii, woi = cs*oii + sn*orr;
                zr[u] = er - woi;
                zi[u] = ei + wor;
            }
            stage0_reg(zr, zi, AR, AI, tws, lt, true);
            sync_sel(1);
            stages14(AR, AI, BR, BI, tws, lt, true, 1);   // result in AR/AI
            // window + overlap-add (double-buffered tail, no extra barrier) + tanh
            float* told = tail + (f & 1)*1024;
            float* tnew = tail + ((f+1) & 1)*1024;
            float2* op = (float2*)(xout + (size_t)f*HOP);
            #pragma unroll
            for (int u = 0; u < 4; u++) {
                int n = lt + u*256;
                float ve = AR[SKW(n)] * scale * hann[2*n];
                float vo = AI[SKW(n)] * scale * hann[2*n+1];
                if (u < 2) {
                    float s0 = told[2*n]   + ve;
                    float s1 = told[2*n+1] + vo;
                    op[n] = make_float2(tanhf(gain*s0), tanhf(gain*s1));
                } else {
                    int j = 2*(n - 512);
                    tnew[j]   = ve;
                    tnew[j+1] = vo;
                }
            }
        } else {
            // prefetch next frame's spectrum
            if (f + 1 < FR) {
                const float2* sg = specg + (size_t)(f+1)*KB;
                float2* sd = specsm + ((f+1) & 1)*KB;
                #pragma unroll
                for (int u = 0; u < 5; u++) {
                    int k = lt + u*256;
                    if (k < KB) sd[k] = sg[k];
                }
            }
        }
        __syncthreads();
    }
}

// ---------------- softmax layer mix + channel sum (float4) ----------------
__global__ void final_kernel(const float* __restrict__ mixer, float* __restrict__ out) {
    int idx = blockIdx.x * 256 + threadIdx.x;
    if (idx >= NB*NT/4) return;
    int b = idx / (NT/4), t4 = idx - b*(NT/4);
    float m0 = mixer[0], m1 = mixer[1], m2 = mixer[2], m3 = mixer[3];
    float mx = fmaxf(fmaxf(m0, m1), fmaxf(m2, m3));
    float e0 = expf(m0-mx), e1 = expf(m1-mx), e2 = expf(m2-mx), e3 = expf(m3-mx);
    float inv = 1.0f / (e0+e1+e2+e3);
    float w[4] = {e0*inv, e1*inv, e2*inv, e3*inv};
    float4 acc = make_float4(0.f,0.f,0.f,0.f);
    for (int c = 0; c < NC; c++) {
        size_t off4 = (size_t)(b*NC + c)*(NT/4) + t4;
        #pragma unroll
        for (int l = 0; l < 4; l++) {
            float4 v = ((const float4*)g_x[l])[off4];
            acc.x += w[l]*v.x; acc.y += w[l]*v.y; acc.z += w[l]*v.z; acc.w += w[l]*v.w;
        }
    }
    ((float4*)out)[idx] = acc;
}

// ---------------- sig passthrough ----------------
__global__ void copy_sig_kernel(const float* __restrict__ sig, float* __restrict__ out) {
    int i = blockIdx.x * 256 + threadIdx.x;
    if (i < NB*NC*NFR) out[NB*NT + i] = sig[i];
}

// ---------------- launch ----------------
extern "C" void kernel_launch(void* const* d_in, const int* in_sizes, int n_in,
                              void* d_out, int out_size) {
    const float* sig        = (const float*)d_in[0];
    const float* noise      = (const float*)d_in[1];
    const float* decays     = (const float*)d_in[2];
    const float* mixer      = (const float*)d_in[3];
    const float* transfers  = (const float*)d_in[4];
    const float* mixer_mats = (const float*)d_in[5];
    const float* gains      = (const float*)d_in[6];
    const float* fb         = (const float*)d_in[7];
    float* out = (float*)d_out;

    cudaFuncSetAttribute(cons_kernel, cudaFuncAttributeMaxDynamicSharedMemorySize, CONS_BYTES);

    init_kernel<<<64, 256>>>(decays);
    ident_kernel<<<NL, 256>>>(mixer_mats);
    tmat_kernel<<<NL*NC, 256>>>(transfers, fb);
    x0_kernel<<<(BC*NT + 255)/256, 256>>>(sig, noise);

    for (int l = 0; l < NL; l++) {
        dim3 mg(NT/256, NB);
        mix_kernel<<<mg, 256>>>(l, mixer_mats + l*NC*NC);   // early-exits when identity
        fwd_kernel<<<BC*FR, 256>>>(l);
        cons_kernel<<<BC, 512, CONS_BYTES>>>(l, gains);
    }

    final_kernel<<<(NB*NT/4 + 255)/256, 256>>>(mixer, out);
    if (out_size >= NB*NT + NB*NC*NFR)
        copy_sig_kernel<<<(NB*NC*NFR + 255)/256, 256>>>(sig, out);
}

// round 10
// speedup vs baseline: 4.2103x; 1.0031x over previous
#include <cuda_runtime.h>
#include <math.h>

// ---------------- problem constants ----------------
#define NB 4            // batch
#define NC 32           // channels
#define NT 131072       // samples
#define NFR 256         // sig frames
#define SPF 512         // samples per sig frame
#define WS 2048         // window size
#define HOP 1024        // step
#define FR 128          // fft frames per signal
#define KB 1025         // rfft bins
#define BC (NB*NC)      // 128
#define NL 3            // layers
#define NH 1024         // complex FFT length (real 2048 packed)

// skewed smem indexing: conflict-free for stride-4m scatter stores
#define SKW(i) ((i) + ((i) >> 5))
#define SSZ (NH + (NH >> 5) + 1)   // 1057

// ---------------- device scratch (static: no runtime allocation) ----------------
__device__ float  g_env[NC*SPF];
__device__ float  g_T[NL*NC*KB];
__device__ float  g_x[NL+1][BC*NT];
__device__ float  g_xm[BC*NT];
__device__ float2 g_spec[BC*FR*KB];     // spectra
__device__ float  g_oa[(size_t)BC*FR*WS]; // windowed frames: [first 1024 | second 1024] per frame
__device__ int    g_ident[NL];

// ---------------- init: envelopes ----------------
__global__ void init_kernel(const float* __restrict__ decays) {
    int tid = blockIdx.x * blockDim.x + threadIdx.x;
    if (tid < NC*SPF) {
        int ch = tid / SPF, j = tid - ch*SPF;
        float base = (float)(SPF-1 - j) * (1.0f/(float)(SPF-1));
        g_env[tid] = powf(base, decays[ch]);
    }
}

// ---------------- identity check for mixer matrices ----------------
__global__ void ident_kernel(const float* __restrict__ M) {
    __shared__ int ok;
    if (threadIdx.x == 0) ok = 1;
    __syncthreads();
    const float* m = M + blockIdx.x * NC*NC;
    for (int i = threadIdx.x; i < NC*NC; i += 256) {
        float expect = ((i / NC) == (i % NC)) ? 1.0f : 0.0f;
        if (m[i] != expect) atomicExch(&ok, 0);
    }
    __syncthreads();
    if (threadIdx.x == 0) g_ident[blockIdx.x] = ok;
}

// ---------------- T = transfers @ filter_bank (exploit ~1% sparsity) ----------------
__global__ void tmat_kernel(const float* __restrict__ transfers, const float* __restrict__ fb) {
    int lc  = blockIdx.x;
    int tid = threadIdx.x;
    const float* tr = transfers + (size_t)lc * KB;
    float acc[5] = {0.f,0.f,0.f,0.f,0.f};
    for (int j = 0; j < KB; j++) {
        float t = tr[j];
        if (t != 0.0f) {
            const float* row = fb + (size_t)j * KB;
            #pragma unroll
            for (int u = 0; u < 5; u++) {
                int k = tid + u*256;
                if (k < KB) acc[u] += t * row[k];
            }
        }
    }
    #pragma unroll
    for (int u = 0; u < 5; u++) {
        int k = tid + u*256;
        if (k < KB) g_T[(size_t)lc*KB + k] = acc[u];
    }
}

// ---------------- excitation ----------------
__global__ void x0_kernel(const float* __restrict__ sig, const float* __restrict__ noise) {
    int idx = blockIdx.x * 256 + threadIdx.x;
    if (idx >= BC*NT) return;
    int bc = idx / NT, t = idx - bc*NT;
    int c = bc & (NC-1);
    int f = t >> 9, j = t & 511;
    g_x[0][idx] = sig[bc*NFR + f] * g_env[c*SPF + j] * noise[t];
}

// ---------------- channel mixing (only runs when mixer_mat != identity) ----------------
__global__ void __launch_bounds__(256) mix_kernel(int layer, const float* __restrict__ M) {
    if (g_ident[layer]) return;
    __shared__ float Ms[NC*NC];
    int b = blockIdx.y, t = blockIdx.x * 256 + threadIdx.x;
    for (int i = threadIdx.x; i < NC*NC; i += 256) Ms[i] = M[i];
    __syncthreads();
    const float* xin = g_x[layer] + (size_t)b*NC*NT + t;
    float xv[NC];
    #pragma unroll
    for (int c = 0; c < NC; c++) xv[c] = xin[(size_t)c*NT];
    float* xo = g_xm + (size_t)b*NC*NT + t;
    #pragma unroll
    for (int d = 0; d < NC; d++) {
        float s = 0.f;
        #pragma unroll
        for (int c = 0; c < NC; c++) s += xv[c] * Ms[c*NC + d];
        xo[(size_t)d*NT] = s;
    }
}

// ---------------- Stockham stages 1..4 (radix-4, 1024 pts, 256 threads); result back in A ----------------
__device__ __forceinline__ void stages14(float* AR, float* AI, float* BR, float* BI,
                                         const float2* tws, int lt, bool inv) {
    float *sR = AR, *sI = AI, *dR = BR, *dI = BI;
    #pragma unroll
    for (int s = 1; s < 5; s++) {
        const int m = 1 << (2*s);
        float ar = sR[SKW(lt)],     ai = sI[SKW(lt)];
        float br = sR[SKW(lt+256)], bi = sI[SKW(lt+256)];
        float cr = sR[SKW(lt+512)], ci = sI[SKW(lt+512)];
        float dr = sR[SKW(lt+768)], di = sI[SKW(lt+768)];
        float apcr = ar+cr, apci = ai+ci, amcr = ar-cr, amci = ai-ci;
        float bpdr = br+dr, bpdi = bi+di, bmdr = br-dr, bmdi = bi-di;
        float t1r, t1i, t3r, t3i;
        if (!inv) { t1r = amcr + bmdi; t1i = amci - bmdr; t3r = amcr - bmdi; t3i = amci + bmdr; }
        else      { t1r = amcr - bmdi; t1i = amci + bmdr; t3r = amcr + bmdi; t3i = amci - bmdr; }
        int j = lt & ~(m-1);
        float2 w = tws[j];
        float w1r = w.x, w1i = inv ? -w.y : w.y;
        float w2r = w1r*w1r - w1i*w1i, w2i = 2.0f*w1r*w1i;
        float w3r = w2r*w1r - w2i*w1i, w3i = w2r*w1i + w2i*w1r;
        int q  = lt & (m-1);
        int ob = q + ((lt >> (2*s)) << (2*s + 2));
        float s2r = apcr - bpdr, s2i = apci - bpdi;
        dR[SKW(ob)]      = apcr + bpdr;         dI[SKW(ob)]      = apci + bpdi;
        dR[SKW(ob+m)]    = t1r*w1r - t1i*w1i;   dI[SKW(ob+m)]    = t1r*w1i + t1i*w1r;
        dR[SKW(ob+2*m)]  = s2r*w2r - s2i*w2i;   dI[SKW(ob+2*m)]  = s2r*w2i + s2i*w2r;
        dR[SKW(ob+3*m)]  = t3r*w3r - t3i*w3i;   dI[SKW(ob+3*m)]  = t3r*w3i + t3i*w3r;
        __syncthreads();
        float* t;
        t = sR; sR = dR; dR = t;
        t = sI; sI = dI; dI = t;
    }
}

// ---------------- stage 0 from registers (m=1): z[lt + u*256] -> buf[4*lt + u] ----------------
__device__ __forceinline__ void stage0_reg(const float* zr, const float* zi,
                                           float* AR, float* AI,
                                           const float2* tws, int lt, bool inv) {
    float apcr = zr[0]+zr[2], apci = zi[0]+zi[2], amcr = zr[0]-zr[2], amci = zi[0]-zi[2];
    float bpdr = zr[1]+zr[3], bpdi = zi[1]+zi[3], bmdr = zr[1]-zr[3], bmdi = zi[1]-zi[3];
    float t1r, t1i, t3r, t3i;
    if (!inv) { t1r = amcr + bmdi; t1i = amci - bmdr; t3r = amcr - bmdi; t3i = amci + bmdr; }
    else      { t1r = amcr - bmdi; t1i = amci + bmdr; t3r = amcr + bmdi; t3i = amci - bmdr; }
    float2 w = tws[lt];
    float w1r = w.x, w1i = inv ? -w.y : w.y;
    float w2r = w1r*w1r - w1i*w1i, w2i = 2.0f*w1r*w1i;
    float w3r = w2r*w1r - w2i*w1i, w3i = w2r*w1i + w2i*w1r;
    float s2r = apcr - bpdr, s2i = apci - bpdi;
    int ob = 4*lt;
    AR[SKW(ob)]   = apcr + bpdr;         AI[SKW(ob)]   = apci + bpdi;
    AR[SKW(ob+1)] = t1r*w1r - t1i*w1i;   AI[SKW(ob+1)] = t1r*w1i + t1i*w1r;
    AR[SKW(ob+2)] = s2r*w2r - s2i*w2i;   AI[SKW(ob+2)] = s2r*w2i + s2i*w2r;
    AR[SKW(ob+3)] = t3r*w3r - t3i*w3i;   AI[SKW(ob+3)] = t3r*w3i + t3i*w3r;
}

// ---------------- forward FFT: one frame per block, window + stage0 fused from global ----------------
__global__ void __launch_bounds__(256) fwd_kernel(int layer) {
    __shared__ float AR[SSZ], AI[SSZ], BR[SSZ], BI[SSZ];
    __shared__ float2 tws[256];
    int blk = blockIdx.x, bc = blk >> 7, f = blk & (FR-1), tid = threadIdx.x;
    { float sn, cs; sincospif(-(float)tid * (1.0f/512.0f), &sn, &cs); tws[tid] = make_float2(cs, sn); }
    const float* src = g_ident[layer] ? g_x[layer] : g_xm;
    const float2* xin2 = (const float2*)(src + (size_t)bc*NT);
    int ibase = f * (HOP/2);
    float zr[4], zi[4];
    #pragma unroll
    for (int u = 0; u < 4; u++) {
        int n = tid + u*256, gi = ibase + n;
        float2 v = (gi < NT/2) ? xin2[gi] : make_float2(0.f, 0.f);
        float he = 0.5f - 0.5f*cospif((float)n * (1.0f/512.0f));            // hann[2n]
        float ho = 0.5f - 0.5f*cospif((float)(2*n+1) * (1.0f/1024.0f));     // hann[2n+1]
        zr[u] = v.x * he;
        zi[u] = v.y * ho;
    }
    stage0_reg(zr, zi, AR, AI, tws, tid, false);
    __syncthreads();
    stages14(AR, AI, BR, BI, tws, tid, false);      // result in AR/AI
    float2* out = g_spec + (size_t)(bc*FR + f)*KB;
    for (int k = tid; k < KB; k += 256) {
        int ka = k & (NH-1), kb = (NH - k) & (NH-1);
        float xr = AR[SKW(ka)], xi = AI[SKW(ka)];
        float yr = AR[SKW(kb)], yi = -AI[SKW(kb)];
        float er  = 0.5f*(xr+yr), ei  = 0.5f*(xi+yi);
        float orr = 0.5f*(xr-yr), oii = 0.5f*(xi-yi);
        float sn, cs; sincospif(-(float)k * (1.0f/1024.0f), &sn, &cs);
        float wor = cs*orr - sn*oii, woi = cs*oii + sn*orr;
        out[k] = make_float2(er + woi, ei - wor);
    }
}

// ---------------- frame recurrence in-place (memory-bound, fully parallel over bc,k) ----------------
__global__ void scan_kernel(int layer) {
    int idx = blockIdx.x * 256 + threadIdx.x;
    if (idx >= BC*KB) return;
    int bc = idx / KB, k = idx - bc*KB;
    int c = bc & (NC-1);
    float T = g_T[(size_t)(layer*NC + c)*KB + k];
    float2 carry = make_float2(0.f, 0.f);
    float2* base = g_spec + (size_t)bc*FR*KB + k;
    #pragma unroll 4
    for (int f = 0; f < FR; f++) {
        float2 v = base[(size_t)f*KB];
        carry.x = (v.x + carry.x) * T;
        carry.y = (v.y + carry.y) * T;
        base[(size_t)f*KB] = carry;
    }
}

// ---------------- inverse FFT: one frame per block; windowed halves to g_oa ----------------
__global__ void __launch_bounds__(256) inv_kernel() {
    __shared__ float AR[SSZ], AI[SSZ], BR[SSZ], BI[SSZ];
    __shared__ float2 X[KB];
    __shared__ float2 tws[256];
    int blk = blockIdx.x, bc = blk >> 7, f = blk & (FR-1), tid = threadIdx.x;
    { float sn, cs; sincospif(-(float)tid * (1.0f/512.0f), &sn, &cs); tws[tid] = make_float2(cs, sn); }
    const float2* slot = g_spec + (size_t)(bc*FR + f)*KB;
    #pragma unroll
    for (int u = 0; u < 5; u++) {
        int k = tid + u*256;
        if (k < KB) X[k] = slot[k];
    }
    __syncthreads();
    // repack X -> Z fused with inverse stage 0
    float zr[4], zi[4];
    #pragma unroll
    for (int u = 0; u < 4; u++) {
        int k = tid + u*256;
        float2 Xa = X[k];
        float2 Yc = X[NH - k];
        float yr = Yc.x, yi = -Yc.y;
        float er  = 0.5f*(Xa.x+yr), ei  = 0.5f*(Xa.y+yi);
        float orr = 0.5f*(Xa.x-yr), oii = 0.5f*(Xa.y-yi);
        float sn, cs; sincospif((float)k * (1.0f/1024.0f), &sn, &cs);   // e^{+i*pi*k/1024}
        float wor = cs*orr - sn*oii, woi = cs*oii + sn*orr;
        zr[u] = er - woi;
        zi[u] = ei + wor;
    }
    stage0_reg(zr, zi, AR, AI, tws, tid, true);
    __syncthreads();
    stages14(AR, AI, BR, BI, tws, tid, true);       // result in AR/AI
    // window + scale; write to aligned g_oa: floats [0..2047] = windowed frame
    float2* outf = (float2*)(g_oa + (size_t)(bc*FR + f)*WS);
    const float scale = 1.0f/(float)NH;
    #pragma unroll
    for (int u = 0; u < 4; u++) {
        int n = tid + u*256;                        // sample pair (2n, 2n+1)
        float he = 0.5f - 0.5f*cospif((float)n * (1.0f/512.0f));
        float ho = 0.5f - 0.5f*cospif((float)(2*n+1) * (1.0f/1024.0f));
        outf[n] = make_float2(AR[SKW(n)] * scale * he, AI[SKW(n)] * scale * ho);
    }
}

// ---------------- combine: overlap-add across adjacent frames + gain*tanh ----------------
__global__ void comb_kernel(int layer, const float* __restrict__ gains) {
    int idx = blockIdx.x * 256 + threadIdx.x;      // float4 index over BC*NT/4
    if (idx >= BC*NT/4) return;
    int bc = idx / (NT/4);
    int t4 = idx - bc*(NT/4);
    int t  = t4 * 4;
    int f  = t >> 10, j = t & 1023;                 // all 4 samples in same 1024-segment
    int c = bc & (NC-1);
    float g = gains[layer*NC + c];
    const float4 first = *(const float4*)(g_oa + (size_t)(bc*FR + f)*WS + j);
    float4 sec = make_float4(0.f,0.f,0.f,0.f);
    if (f > 0)
        sec = *(const float4*)(g_oa + (size_t)(bc*FR + f - 1)*WS + 1024 + j);
    float4 o;
    o.x = tanhf(g*(first.x + sec.x));
    o.y = tanhf(g*(first.y + sec.y));
    o.z = tanhf(g*(first.z + sec.z));
    o.w = tanhf(g*(first.w + sec.w));
    ((float4*)(g_x[layer+1] + (size_t)bc*NT))[t4] = o;
}

// ---------------- softmax layer mix + channel sum (float4) ----------------
__global__ void final_kernel(const float* __restrict__ mixer, float* __restrict__ out) {
    int idx = blockIdx.x * 256 + threadIdx.x;
    if (idx >= NB*NT/4) return;
    int b = idx / (NT/4), t4 = idx - b*(NT/4);
    float m0 = mixer[0], m1 = mixer[1], m2 = mixer[2], m3 = mixer[3];
    float mx = fmaxf(fmaxf(m0, m1), fmaxf(m2, m3));
    float e0 = expf(m0-mx), e1 = expf(m1-mx), e2 = expf(m2-mx), e3 = expf(m3-mx);
    float inv = 1.0f / (e0+e1+e2+e3);
    float w[4] = {e0*inv, e1*inv, e2*inv, e3*inv};
    float4 acc = make_float4(0.f,0.f,0.f,0.f);
    for (int c = 0; c < NC; c++) {
        size_t off4 = (size_t)(b*NC + c)*(NT/4) + t4;
        #pragma unroll
        for (int l = 0; l < 4; l++) {
            float4 v = ((const float4*)g_x[l])[off4];
            acc.x += w[l]*v.x; acc.y += w[l]*v.y; acc.z += w[l]*v.z; acc.w += w[l]*v.w;
        }
    }
    ((float4*)out)[idx] = acc;
}

// ---------------- sig passthrough ----------------
__global__ void copy_sig_kernel(const float* __restrict__ sig, float* __restrict__ out) {
    int i = blockIdx.x * 256 + threadIdx.x;
    if (i < NB*NC*NFR) out[NB*NT + i] = sig[i];
}

// ---------------- launch ----------------
extern "C" void kernel_launch(void* const* d_in, const int* in_sizes, int n_in,
                              void* d_out, int out_size) {
    const float* sig        = (const float*)d_in[0];
    const float* noise      = (const float*)d_in[1];
    const float* decays     = (const float*)d_in[2];
    const float* mixer      = (const float*)d_in[3];
    const float* transfers  = (const float*)d_in[4];
    const float* mixer_mats = (const float*)d_in[5];
    const float* gains      = (const float*)d_in[6];
    const float* fb         = (const float*)d_in[7];
    float* out = (float*)d_out;

    init_kernel<<<64, 256>>>(decays);
    ident_kernel<<<NL, 256>>>(mixer_mats);
    tmat_kernel<<<NL*NC, 256>>>(transfers, fb);
    x0_kernel<<<(BC*NT + 255)/256, 256>>>(sig, noise);

    for (int l = 0; l < NL; l++) {
        dim3 mg(NT/256, NB);
        mix_kernel<<<mg, 256>>>(l, mixer_mats + l*NC*NC);   // early-exits when identity
        fwd_kernel<<<BC*FR, 256>>>(l);
        scan_kernel<<<(BC*KB + 255)/256, 256>>>(l);
        inv_kernel<<<BC*FR, 256>>>();
        comb_kernel<<<(BC*NT/4 + 255)/256, 256>>>(l, gains);
    }

    final_kernel<<<(NB*NT/4 + 255)/256, 256>>>(mixer, out);
    if (out_size >= NB*NT + NB*NC*NFR)
        copy_sig_kernel<<<(NB*NC*NFR + 255)/256, 256>>>(sig, out);
}

// round 11
// speedup vs baseline: 4.8262x; 1.1463x over previous
#include <cuda_runtime.h>
#include <math.h>

// ---------------- problem constants ----------------
#define NB 4            // batch
#define NC 32           // channels
#define NT 131072       // samples
#define NFR 256         // sig frames
#define SPF 512         // samples per sig frame
#define WS 2048         // window size
#define HOP 1024        // step
#define FR 128          // fft frames per signal
#define KB 1025         // rfft bins
#define BC (NB*NC)      // 128
#define NL 3            // layers
#define NH 1024         // complex FFT length (real 2048 packed)
#define CH 16           // chunks per signal
#define FPC 8           // frames per chunk

// skewed smem indexing: conflict-free for stride-4m scatter stores
#define SKW(i) ((i) + ((i) >> 5))
#define SSZ (NH + (NH >> 5) + 1)   // 1057

// sweep kernel dynamic smem (floats):
//  float2 X[KB], tw2[NH], tws[256]; float AR,AI,BR,BI[SSZ], hann[WS], prevsec[2][1024]
#define SWEEP_FLOATS (2*(KB + NH + 256) + 4*SSZ + WS + 2048)
#define SWEEP_BYTES (SWEEP_FLOATS * 4)

// ---------------- device scratch (static: no runtime allocation) ----------------
__device__ float  g_env[NC*SPF];
__device__ float  g_T[NL*NC*KB];
__device__ float  g_x[NL+1][BC*NT];
__device__ float  g_xm[BC*NT];
__device__ float2 g_spec[BC*FR*KB];          // spectra
__device__ float2 g_carry[CH*BC*KB];         // chunk-entry carries (ch=0 unused)
__device__ float2 g_bnd_first[BC*CH*512];    // chunk-first-frame first half (pairs)
__device__ float2 g_bnd_sec[BC*CH*512];      // chunk-last-frame second half (pairs)
__device__ int    g_ident[NL];

// ---------------- init: envelopes ----------------
__global__ void init_kernel(const float* __restrict__ decays) {
    int tid = blockIdx.x * blockDim.x + threadIdx.x;
    if (tid < NC*SPF) {
        int ch = tid / SPF, j = tid - ch*SPF;
        float base = (float)(SPF-1 - j) * (1.0f/(float)(SPF-1));
        g_env[tid] = powf(base, decays[ch]);
    }
}

// ---------------- identity check for mixer matrices ----------------
__global__ void ident_kernel(const float* __restrict__ M) {
    __shared__ int ok;
    if (threadIdx.x == 0) ok = 1;
    __syncthreads();
    const float* m = M + blockIdx.x * NC*NC;
    for (int i = threadIdx.x; i < NC*NC; i += 256) {
        float expect = ((i / NC) == (i % NC)) ? 1.0f : 0.0f;
        if (m[i] != expect) atomicExch(&ok, 0);
    }
    __syncthreads();
    if (threadIdx.x == 0) g_ident[blockIdx.x] = ok;
}

// ---------------- T = transfers @ filter_bank (exploit ~1% sparsity) ----------------
__global__ void tmat_kernel(const float* __restrict__ transfers, const float* __restrict__ fb) {
    int lc  = blockIdx.x;
    int tid = threadIdx.x;
    const float* tr = transfers + (size_t)lc * KB;
    float acc[5] = {0.f,0.f,0.f,0.f,0.f};
    for (int j = 0; j < KB; j++) {
        float t = tr[j];
        if (t != 0.0f) {
            const float* row = fb + (size_t)j * KB;
            #pragma unroll
            for (int u = 0; u < 5; u++) {
                int k = tid + u*256;
                if (k < KB) acc[u] += t * row[k];
            }
        }
    }
    #pragma unroll
    for (int u = 0; u < 5; u++) {
        int k = tid + u*256;
        if (k < KB) g_T[(size_t)lc*KB + k] = acc[u];
    }
}

// ---------------- excitation (float4) ----------------
__global__ void x0_kernel(const float* __restrict__ sig, const float* __restrict__ noise) {
    int idx = blockIdx.x * 256 + threadIdx.x;       // float4 index
    if (idx >= BC*NT/4) return;
    int bc = idx / (NT/4), t4 = idx - bc*(NT/4);
    int t  = t4 * 4;
    int c = bc & (NC-1);
    int f = t >> 9, j = t & 511;
    float s = sig[bc*NFR + f];
    float4 nz = ((const float4*)noise)[t4];
    float4 ev = ((const float4*)g_env)[c*(SPF/4) + (j >> 2)];
    float4 o;
    o.x = s * ev.x * nz.x;  o.y = s * ev.y * nz.y;
    o.z = s * ev.z * nz.z;  o.w = s * ev.w * nz.w;
    ((float4*)(g_x[0] + (size_t)bc*NT))[t4] = o;
}

// ---------------- channel mixing (only runs when mixer_mat != identity) ----------------
__global__ void __launch_bounds__(256) mix_kernel(int layer, const float* __restrict__ M) {
    if (g_ident[layer]) return;
    __shared__ float Ms[NC*NC];
    int b = blockIdx.y, t = blockIdx.x * 256 + threadIdx.x;
    for (int i = threadIdx.x; i < NC*NC; i += 256) Ms[i] = M[i];
    __syncthreads();
    const float* xin = g_x[layer] + (size_t)b*NC*NT + t;
    float xv[NC];
    #pragma unroll
    for (int c = 0; c < NC; c++) xv[c] = xin[(size_t)c*NT];
    float* xo = g_xm + (size_t)b*NC*NT + t;
    #pragma unroll
    for (int d = 0; d < NC; d++) {
        float s = 0.f;
        #pragma unroll
        for (int c = 0; c < NC; c++) s += xv[c] * Ms[c*NC + d];
        xo[(size_t)d*NT] = s;
    }
}

// ---------------- Stockham stages 1..4 (radix-4, 1024 pts, 256 threads); result back in A ----------------
__device__ __forceinline__ void stages14(float* AR, float* AI, float* BR, float* BI,
                                         const float2* tws, int lt, bool inv) {
    float *sR = AR, *sI = AI, *dR = BR, *dI = BI;
    #pragma unroll
    for (int s = 1; s < 5; s++) {
        const int m = 1 << (2*s);
        float ar = sR[SKW(lt)],     ai = sI[SKW(lt)];
        float br = sR[SKW(lt+256)], bi = sI[SKW(lt+256)];
        float cr = sR[SKW(lt+512)], ci = sI[SKW(lt+512)];
        float dr = sR[SKW(lt+768)], di = sI[SKW(lt+768)];
        float apcr = ar+cr, apci = ai+ci, amcr = ar-cr, amci = ai-ci;
        float bpdr = br+dr, bpdi = bi+di, bmdr = br-dr, bmdi = bi-di;
        float t1r, t1i, t3r, t3i;
        if (!inv) { t1r = amcr + bmdi; t1i = amci - bmdr; t3r = amcr - bmdi; t3i = amci + bmdr; }
        else      { t1r = amcr - bmdi; t1i = amci + bmdr; t3r = amcr + bmdi; t3i = amci - bmdr; }
        int j = lt & ~(m-1);
        float2 w = tws[j];
        float w1r = w.x, w1i = inv ? -w.y : w.y;
        float w2r = w1r*w1r - w1i*w1i, w2i = 2.0f*w1r*w1i;
        float w3r = w2r*w1r - w2i*w1i, w3i = w2r*w1i + w2i*w1r;
        int q  = lt & (m-1);
        int ob = q + ((lt >> (2*s)) << (2*s + 2));
        float s2r = apcr - bpdr, s2i = apci - bpdi;
        dR[SKW(ob)]      = apcr + bpdr;         dI[SKW(ob)]      = apci + bpdi;
        dR[SKW(ob+m)]    = t1r*w1r - t1i*w1i;   dI[SKW(ob+m)]    = t1r*w1i + t1i*w1r;
        dR[SKW(ob+2*m)]  = s2r*w2r - s2i*w2i;   dI[SKW(ob+2*m)]  = s2r*w2i + s2i*w2r;
        dR[SKW(ob+3*m)]  = t3r*w3r - t3i*w3i;   dI[SKW(ob+3*m)]  = t3r*w3i + t3i*w3r;
        __syncthreads();
        float* t;
        t = sR; sR = dR; dR = t;
        t = sI; sI = dI; dI = t;
    }
}

// ---------------- stage 0 from registers (m=1): z[lt + u*256] -> buf[4*lt + u] ----------------
__device__ __forceinline__ void stage0_reg(const float* zr, const float* zi,
                                           float* AR, float* AI,
                                           const float2* tws, int lt, bool inv) {
    float apcr = zr[0]+zr[2], apci = zi[0]+zi[2], amcr = zr[0]-zr[2], amci = zi[0]-zi[2];
    float bpdr = zr[1]+zr[3], bpdi = zi[1]+zi[3], bmdr = zr[1]-zr[3], bmdi = zi[1]-zi[3];
    float t1r, t1i, t3r, t3i;
    if (!inv) { t1r = amcr + bmdi; t1i = amci - bmdr; t3r = amcr - bmdi; t3i = amci + bmdr; }
    else      { t1r = amcr - bmdi; t1i = amci + bmdr; t3r = amcr + bmdi; t3i = amci - bmdr; }
    float2 w = tws[lt];
    float w1r = w.x, w1i = inv ? -w.y : w.y;
    float w2r = w1r*w1r - w1i*w1i, w2i = 2.0f*w1r*w1i;
    float w3r = w2r*w1r - w2i*w1i, w3i = w2r*w1i + w2i*w1r;
    float s2r = apcr - bpdr, s2i = apci - bpdi;
    int ob = 4*lt;
    AR[SKW(ob)]   = apcr + bpdr;         AI[SKW(ob)]   = apci + bpdi;
    AR[SKW(ob+1)] = t1r*w1r - t1i*w1i;   AI[SKW(ob+1)] = t1r*w1i + t1i*w1r;
    AR[SKW(ob+2)] = s2r*w2r - s2i*w2i;   AI[SKW(ob+2)] = s2r*w2i + s2i*w2r;
    AR[SKW(ob+3)] = t3r*w3r - t3i*w3i;   AI[SKW(ob+3)] = t3r*w3i + t3i*w3r;
}

// ---------------- forward FFT: one frame per block, window + stage0 fused from global ----------------
__global__ void __launch_bounds__(256) fwd_kernel(int layer) {
    __shared__ float AR[SSZ], AI[SSZ], BR[SSZ], BI[SSZ];
    __shared__ float2 tws[256];
    int blk = blockIdx.x, bc = blk >> 7, f = blk & (FR-1), tid = threadIdx.x;
    { float sn, cs; sincospif(-(float)tid * (1.0f/512.0f), &sn, &cs); tws[tid] = make_float2(cs, sn); }
    const float* src = g_ident[layer] ? g_x[layer] : g_xm;
    const float2* xin2 = (const float2*)(src + (size_t)bc*NT);
    int ibase = f * (HOP/2);
    float zr[4], zi[4];
    #pragma unroll
    for (int u = 0; u < 4; u++) {
        int n = tid + u*256, gi = ibase + n;
        float2 v = (gi < NT/2) ? xin2[gi] : make_float2(0.f, 0.f);
        float he = 0.5f - 0.5f*cospif((float)n * (1.0f/512.0f));            // hann[2n]
        float ho = 0.5f - 0.5f*cospif((float)(2*n+1) * (1.0f/1024.0f));     // hann[2n+1]
        zr[u] = v.x * he;
        zi[u] = v.y * ho;
    }
    stage0_reg(zr, zi, AR, AI, tws, tid, false);
    __syncthreads();
    stages14(AR, AI, BR, BI, tws, tid, false);      // result in AR/AI
    float2* out = g_spec + (size_t)(bc*FR + f)*KB;
    for (int k = tid; k < KB; k += 256) {
        int ka = k & (NH-1), kb = (NH - k) & (NH-1);
        float xr = AR[SKW(ka)], xi = AI[SKW(ka)];
        float yr = AR[SKW(kb)], yi = -AI[SKW(kb)];
        float er  = 0.5f*(xr+yr), ei  = 0.5f*(xi+yi);
        float orr = 0.5f*(xr-yr), oii = 0.5f*(xi-yi);
        float sn, cs; sincospif(-(float)k * (1.0f/1024.0f), &sn, &cs);
        float wor = cs*orr - sn*oii, woi = cs*oii + sn*orr;
        out[k] = make_float2(er + woi, ei - wor);
    }
}

// ---------------- chunk-boundary carries for the frame recurrence ----------------
__global__ void carry_kernel(int layer) {
    int idx = blockIdx.x * 256 + threadIdx.x;
    if (idx >= BC*KB) return;
    int bc = idx / KB, k = idx - bc*KB;
    int c = bc & (NC-1);
    float T = g_T[(size_t)(layer*NC + c)*KB + k];
    float2 cr = make_float2(0.f, 0.f);
    const float2* base = g_spec + (size_t)bc*FR*KB + k;
    for (int f = 0; f < FR - FPC; f++) {
        float2 v = base[(size_t)f*KB];
        cr.x = (v.x + cr.x) * T;
        cr.y = (v.y + cr.y) * T;
        if (((f+1) & (FPC-1)) == 0)
            g_carry[(size_t)((f+1)/FPC)*BC*KB + idx] = cr;
    }
}

// ---------------- sweep: per (bc, chunk): scan + inverse FFT + window + OA + tanh ----------------
__global__ void __launch_bounds__(256) sweep_kernel(int layer, const float* __restrict__ gains) {
    extern __shared__ float sm[];
    float2* X    = (float2*)sm;          // [KB]
    float2* tw2  = X + KB;               // [NH] e^{+i*pi*k/1024}
    float2* tws  = tw2 + NH;             // [256]
    float*  fb   = (float*)(tws + 256);
    float* AR = fb;            float* AI = fb + SSZ;
    float* BR = fb + 2*SSZ;    float* BI = fb + 3*SSZ;
    float* hann = fb + 4*SSZ;            // [2048]
    float* prevsec = hann + WS;          // [2][1024]

    int blk = blockIdx.x;
    int bc = blk >> 4, ch = blk & (CH-1);
    int lt = threadIdx.x;
    int c = bc & (NC-1);
    float gain = gains[layer*NC + c];

    { float sn, cs; sincospif(-(float)lt * (1.0f/512.0f), &sn, &cs); tws[lt] = make_float2(cs, sn); }
    #pragma unroll
    for (int u = 0; u < 4; u++) {
        int k = lt + u*256;
        float sn, cs; sincospif((float)k * (1.0f/1024.0f), &sn, &cs);
        tw2[k] = make_float2(cs, sn);
    }
    #pragma unroll
    for (int u = 0; u < 8; u++) {
        int i = lt + u*256;
        hann[i] = 0.5f - 0.5f*cospif((float)i * (1.0f/1024.0f));
    }

    // per-thread T + carry registers for k = lt + u*256
    float Treg[5]; float2 creg[5];
    #pragma unroll
    for (int u = 0; u < 5; u++) {
        int k = lt + u*256;
        if (k < KB) {
            Treg[u] = g_T[(size_t)(layer*NC + c)*KB + k];
            creg[u] = ch ? g_carry[(size_t)ch*BC*KB + (size_t)bc*KB + k] : make_float2(0.f, 0.f);
        }
    }

    const float2* specb = g_spec + (size_t)bc*FR*KB + (size_t)(ch*FPC)*KB;
    float* xout = g_x[layer+1] + (size_t)bc*NT;
    const float scale = 1.0f/(float)NH;

    // prefetch first frame
    float2 rv[5];
    #pragma unroll
    for (int u = 0; u < 5; u++) {
        int k = lt + u*256;
        if (k < KB) rv[u] = specb[k];
    }
    __syncthreads();

    for (int fi = 0; fi < FPC; fi++) {
        int f = ch*FPC + fi;
        // scan update into X (from prefetched registers)
        #pragma unroll
        for (int u = 0; u < 5; u++) {
            int k = lt + u*256;
            if (k < KB) {
                creg[u].x = (rv[u].x + creg[u].x) * Treg[u];
                creg[u].y = (rv[u].y + creg[u].y) * Treg[u];
                X[k] = creg[u];
            }
        }
        __syncthreads();
        // prefetch next frame (latency hidden behind FFT)
        if (fi + 1 < FPC) {
            const float2* sp = specb + (size_t)(fi+1)*KB;
            #pragma unroll
            for (int u = 0; u < 5; u++) {
                int k = lt + u*256;
                if (k < KB) rv[u] = sp[k];
            }
        }
        // repack X -> Z fused with inverse stage 0
        float zr[4], zi[4];
        #pragma unroll
        for (int u = 0; u < 4; u++) {
            int k = lt + u*256;
            float2 Xa = X[k];
            float2 Yc = X[NH - k];
            float yr = Yc.x, yi = -Yc.y;
            float er  = 0.5f*(Xa.x+yr), ei  = 0.5f*(Xa.y+yi);
            float orr = 0.5f*(Xa.x-yr), oii = 0.5f*(Xa.y-yi);
            float cs = tw2[k].x, sn = tw2[k].y;
            float wor = cs*orr - sn*oii, woi = cs*oii + sn*orr;
            zr[u] = er - woi;
            zi[u] = ei + wor;
        }
        stage0_reg(zr, zi, AR, AI, tws, lt, true);
        __syncthreads();
        stages14(AR, AI, BR, BI, tws, lt, true);   // result in AR/AI
        // window + in-block overlap-add + tanh
        float ve[4], vo[4];
        #pragma unroll
        for (int u = 0; u < 4; u++) {
            int n = lt + u*256;
            ve[u] = AR[SKW(n)] * scale * hann[2*n];
            vo[u] = AI[SKW(n)] * scale * hann[2*n+1];
        }
        float* rd = prevsec + (fi & 1)*1024;
        float* wr = prevsec + ((fi+1) & 1)*1024;
        if (fi > 0) {
            float2* out2 = (float2*)xout + (size_t)f*512;
            #pragma unroll
            for (int u = 0; u < 2; u++) {
                int n = lt + u*256;
                float s0 = rd[2*n]   + ve[u];
                float s1 = rd[2*n+1] + vo[u];
                out2[n] = make_float2(tanhf(gain*s0), tanhf(gain*s1));
            }
        } else {
            float2* bf = g_bnd_first + (size_t)(bc*CH + ch)*512;
            #pragma unroll
            for (int u = 0; u < 2; u++) {
                int n = lt + u*256;
                bf[n] = make_float2(ve[u], vo[u]);
            }
        }
        #pragma unroll
        for (int u = 2; u < 4; u++) {
            int n = lt + u*256;
            int j = 2*(n - 512);
            wr[j]   = ve[u];
            wr[j+1] = vo[u];
        }
        if (fi == FPC-1) {
            float2* bs = g_bnd_sec + (size_t)(bc*CH + ch)*512;
            #pragma unroll
            for (int u = 2; u < 4; u++) {
                int n = lt + u*256;
                bs[n - 512] = make_float2(ve[u], vo[u]);
            }
        }
        __syncthreads();
    }
}

// ---------------- stitch: chunk-boundary segments ----------------
__global__ void stitch_kernel(int layer, const float* __restrict__ gains) {
    int idx = blockIdx.x * 256 + threadIdx.x;       // float2 index over BC*CH*512
    if (idx >= BC*CH*512) return;
    int bc = idx / (CH*512);
    int r  = idx - bc*(CH*512);
    int ch = r >> 9, m = r & 511;
    int c = bc & (NC-1);
    float g = gains[layer*NC + c];
    float2 fv = g_bnd_first[idx];
    float2 sv = make_float2(0.f, 0.f);
    if (ch > 0) sv = g_bnd_sec[(size_t)(bc*CH + ch - 1)*512 + m];
    float2 o = make_float2(tanhf(g*(fv.x + sv.x)), tanhf(g*(fv.y + sv.y)));
    ((float2*)(g_x[layer+1] + (size_t)bc*NT))[(size_t)ch*FPC*512 + m] = o;
}

// ---------------- softmax layer mix + channel sum (float4) ----------------
__global__ void final_kernel(const float* __restrict__ mixer, float* __restrict__ out) {
    int idx = blockIdx.x * 256 + threadIdx.x;
    if (idx >= NB*NT/4) return;
    int b = idx / (NT/4), t4 = idx - b*(NT/4);
    float m0 = mixer[0], m1 = mixer[1], m2 = mixer[2], m3 = mixer[3];
    float mx = fmaxf(fmaxf(m0, m1), fmaxf(m2, m3));
    float e0 = expf(m0-mx), e1 = expf(m1-mx), e2 = expf(m2-mx), e3 = expf(m3-mx);
    float inv = 1.0f / (e0+e1+e2+e3);
    float w[4] = {e0*inv, e1*inv, e2*inv, e3*inv};
    float4 acc = make_float4(0.f,0.f,0.f,0.f);
    for (int c = 0; c < NC; c++) {
        size_t off4 = (size_t)(b*NC + c)*(NT/4) + t4;
        #pragma unroll
        for (int l = 0; l < 4; l++) {
            float4 v = ((const float4*)g_x[l])[off4];
            acc.x += w[l]*v.x; acc.y += w[l]*v.y; acc.z += w[l]*v.z; acc.w += w[l]*v.w;
        }
    }
    ((float4*)out)[idx] = acc;
}

// ---------------- sig passthrough ----------------
__global__ void copy_sig_kernel(const float* __restrict__ sig, float* __restrict__ out) {
    int i = blockIdx.x * 256 + threadIdx.x;
    if (i < NB*NC*NFR) out[NB*NT + i] = sig[i];
}

// ---------------- launch ----------------
extern "C" void kernel_launch(void* const* d_in, const int* in_sizes, int n_in,
                              void* d_out, int out_size) {
    const float* sig        = (const float*)d_in[0];
    const float* noise      = (const float*)d_in[1];
    const float* decays     = (const float*)d_in[2];
    const float* mixer      = (const float*)d_in[3];
    const float* transfers  = (const float*)d_in[4];
    const float* mixer_mats = (const float*)d_in[5];
    const float* gains      = (const float*)d_in[6];
    const float* fb         = (const float*)d_in[7];
    float* out = (float*)d_out;

    cudaFuncSetAttribute(sweep_kernel, cudaFuncAttributeMaxDynamicSharedMemorySize, SWEEP_BYTES);

    init_kernel<<<64, 256>>>(decays);
    ident_kernel<<<NL, 256>>>(mixer_mats);
    tmat_kernel<<<NL*NC, 256>>>(transfers, fb);
    x0_kernel<<<(BC*NT/4 + 255)/256, 256>>>(sig, noise);

    for (int l = 0; l < NL; l++) {
        dim3 mg(NT/256, NB);
        mix_kernel<<<mg, 256>>>(l, mixer_mats + l*NC*NC);   // early-exits when identity
        fwd_kernel<<<BC*FR, 256>>>(l);
        carry_kernel<<<(BC*KB + 255)/256, 256>>>(l);
        sweep_kernel<<<BC*CH, 256, SWEEP_BYTES>>>(l, gains);
        stitch_kernel<<<(BC*CH*512 + 255)/256, 256>>>(l, gains);
    }

    final_kernel<<<(NB*NT/4 + 255)/256, 256>>>(mixer, out);
    if (out_size >= NB*NT + NB*NC*NFR)
        copy_sig_kernel<<<(NB*NC*NFR + 255)/256, 256>>>(sig, out);
}

// round 12
// speedup vs baseline: 5.3673x; 1.1121x over previous
#include <cuda_runtime.h>
#include <math.h>

// ---------------- problem constants ----------------
#define NB 4            // batch
#define NC 32           // channels
#define NT 131072       // samples
#define NFR 256         // sig frames
#define SPF 512         // samples per sig frame
#define WS 2048         // window size
#define HOP 1024        // step
#define FR 128          // fft frames per signal
#define KB 1025         // rfft bins
#define BC (NB*NC)      // 128
#define NL 3            // layers
#define NH 1024         // complex FFT length (real 2048 packed)
#define CH 16           // chunks per signal
#define FPC 8           // frames per chunk

// skewed smem indexing: conflict-free for stride-4m scatter stores
#define SKW(i) ((i) + ((i) >> 5))
#define SSZ (NH + (NH >> 5) + 1)   // 1057

// sweep kernel dynamic smem (floats): float2 X[KB]; float AR,AI,BR,BI[SSZ]; prevsec[2][1024]
#define SWEEP_FLOATS (2*KB + 4*SSZ + 2048)
#define SWEEP_BYTES (SWEEP_FLOATS * 4)

// ---------------- device scratch (static: no runtime allocation) ----------------
__device__ float  g_env[NC*SPF];
__device__ float  g_T[NL*NC*KB];
__device__ float  g_x[NL+1][BC*NT];
__device__ float  g_xm[BC*NT];
__device__ float2 g_spec[BC*FR*KB];          // spectra
__device__ float2 g_carry[CH*BC*KB];         // chunk-entry carries (ch=0 unused)
__device__ float2 g_bnd_first[BC*CH*512];    // chunk-first-frame first half (pairs)
__device__ float2 g_bnd_sec[BC*CH*512];      // chunk-last-frame second half (pairs)
__device__ int    g_ident[NL];

// ---------------- init: envelopes ----------------
__global__ void init_kernel(const float* __restrict__ decays) {
    int tid = blockIdx.x * blockDim.x + threadIdx.x;
    if (tid < NC*SPF) {
        int ch = tid / SPF, j = tid - ch*SPF;
        float base = (float)(SPF-1 - j) * (1.0f/(float)(SPF-1));
        g_env[tid] = powf(base, decays[ch]);
    }
}

// ---------------- identity check for mixer matrices ----------------
__global__ void ident_kernel(const float* __restrict__ M) {
    __shared__ int ok;
    if (threadIdx.x == 0) ok = 1;
    __syncthreads();
    const float* m = M + blockIdx.x * NC*NC;
    for (int i = threadIdx.x; i < NC*NC; i += 256) {
        float expect = ((i / NC) == (i % NC)) ? 1.0f : 0.0f;
        if (m[i] != expect) atomicExch(&ok, 0);
    }
    __syncthreads();
    if (threadIdx.x == 0) g_ident[blockIdx.x] = ok;
}

// ---------------- T = transfers @ filter_bank (exploit ~1% sparsity) ----------------
__global__ void tmat_kernel(const float* __restrict__ transfers, const float* __restrict__ fb) {
    int lc  = blockIdx.x;
    int tid = threadIdx.x;
    const float* tr = transfers + (size_t)lc * KB;
    float acc[5] = {0.f,0.f,0.f,0.f,0.f};
    for (int j = 0; j < KB; j++) {
        float t = tr[j];
        if (t != 0.0f) {
            const float* row = fb + (size_t)j * KB;
            #pragma unroll
            for (int u = 0; u < 5; u++) {
                int k = tid + u*256;
                if (k < KB) acc[u] += t * row[k];
            }
        }
    }
    #pragma unroll
    for (int u = 0; u < 5; u++) {
        int k = tid + u*256;
        if (k < KB) g_T[(size_t)lc*KB + k] = acc[u];
    }
}

// ---------------- excitation (float4) ----------------
__global__ void x0_kernel(const float* __restrict__ sig, const float* __restrict__ noise) {
    int idx = blockIdx.x * 256 + threadIdx.x;       // float4 index
    if (idx >= BC*NT/4) return;
    int bc = idx / (NT/4), t4 = idx - bc*(NT/4);
    int t  = t4 * 4;
    int c = bc & (NC-1);
    int f = t >> 9, j = t & 511;
    float s = sig[bc*NFR + f];
    float4 nz = ((const float4*)noise)[t4];
    float4 ev = ((const float4*)g_env)[c*(SPF/4) + (j >> 2)];
    float4 o;
    o.x = s * ev.x * nz.x;  o.y = s * ev.y * nz.y;
    o.z = s * ev.z * nz.z;  o.w = s * ev.w * nz.w;
    ((float4*)(g_x[0] + (size_t)bc*NT))[t4] = o;
}

// ---------------- channel mixing (only runs when mixer_mat != identity) ----------------
__global__ void __launch_bounds__(256) mix_kernel(int layer, const float* __restrict__ M) {
    if (g_ident[layer]) return;
    __shared__ float Ms[NC*NC];
    int b = blockIdx.y, t = blockIdx.x * 256 + threadIdx.x;
    for (int i = threadIdx.x; i < NC*NC; i += 256) Ms[i] = M[i];
    __syncthreads();
    const float* xin = g_x[layer] + (size_t)b*NC*NT + t;
    float xv[NC];
    #pragma unroll
    for (int c = 0; c < NC; c++) xv[c] = xin[(size_t)c*NT];
    float* xo = g_xm + (size_t)b*NC*NT + t;
    #pragma unroll
    for (int d = 0; d < NC; d++) {
        float s = 0.f;
        #pragma unroll
        for (int c = 0; c < NC; c++) s += xv[c] * Ms[c*NC + d];
        xo[(size_t)d*NT] = s;
    }
}

// ---------------- Stockham stages 1..4 (radix-4, forward, table twiddles) ----------------
__device__ __forceinline__ void stages14(float* AR, float* AI, float* BR, float* BI,
                                         const float2* tws, int lt, bool inv) {
    float *sR = AR, *sI = AI, *dR = BR, *dI = BI;
    #pragma unroll
    for (int s = 1; s < 5; s++) {
        const int m = 1 << (2*s);
        float ar = sR[SKW(lt)],     ai = sI[SKW(lt)];
        float br = sR[SKW(lt+256)], bi = sI[SKW(lt+256)];
        float cr = sR[SKW(lt+512)], ci = sI[SKW(lt+512)];
        float dr = sR[SKW(lt+768)], di = sI[SKW(lt+768)];
        float apcr = ar+cr, apci = ai+ci, amcr = ar-cr, amci = ai-ci;
        float bpdr = br+dr, bpdi = bi+di, bmdr = br-dr, bmdi = bi-di;
        float t1r, t1i, t3r, t3i;
        if (!inv) { t1r = amcr + bmdi; t1i = amci - bmdr; t3r = amcr - bmdi; t3i = amci + bmdr; }
        else      { t1r = amcr - bmdi; t1i = amci + bmdr; t3r = amcr + bmdi; t3i = amci - bmdr; }
        int j = lt & ~(m-1);
        float2 w = tws[j];
        float w1r = w.x, w1i = inv ? -w.y : w.y;
        float w2r = w1r*w1r - w1i*w1i, w2i = 2.0f*w1r*w1i;
        float w3r = w2r*w1r - w2i*w1i, w3i = w2r*w1i + w2i*w1r;
        int q  = lt & (m-1);
        int ob = q + ((lt >> (2*s)) << (2*s + 2));
        float s2r = apcr - bpdr, s2i = apci - bpdi;
        dR[SKW(ob)]      = apcr + bpdr;         dI[SKW(ob)]      = apci + bpdi;
        dR[SKW(ob+m)]    = t1r*w1r - t1i*w1i;   dI[SKW(ob+m)]    = t1r*w1i + t1i*w1r;
        dR[SKW(ob+2*m)]  = s2r*w2r - s2i*w2i;   dI[SKW(ob+2*m)]  = s2r*w2i + s2i*w2r;
        dR[SKW(ob+3*m)]  = t3r*w3r - t3i*w3i;   dI[SKW(ob+3*m)]  = t3r*w3i + t3i*w3r;
        __syncthreads();
        float* t;
        t = sR; sR = dR; dR = t;
        t = sI; sI = dI; dI = t;
    }
}

// ---------------- stage 0 from registers (forward, table twiddle) ----------------
__device__ __forceinline__ void stage0_reg(const float* zr, const float* zi,
                                           float* AR, float* AI,
                                           const float2* tws, int lt, bool inv) {
    float apcr = zr[0]+zr[2], apci = zi[0]+zi[2], amcr = zr[0]-zr[2], amci = zi[0]-zi[2];
    float bpdr = zr[1]+zr[3], bpdi = zi[1]+zi[3], bmdr = zr[1]-zr[3], bmdi = zi[1]-zi[3];
    float t1r, t1i, t3r, t3i;
    if (!inv) { t1r = amcr + bmdi; t1i = amci - bmdr; t3r = amcr - bmdi; t3i = amci + bmdr; }
    else      { t1r = amcr - bmdi; t1i = amci + bmdr; t3r = amcr + bmdi; t3i = amci - bmdr; }
    float2 w = tws[lt];
    float w1r = w.x, w1i = inv ? -w.y : w.y;
    float w2r = w1r*w1r - w1i*w1i, w2i = 2.0f*w1r*w1i;
    float w3r = w2r*w1r - w2i*w1i, w3i = w2r*w1i + w2i*w1r;
    float s2r = apcr - bpdr, s2i = apci - bpdi;
    int ob = 4*lt;
    AR[SKW(ob)]   = apcr + bpdr;         AI[SKW(ob)]   = apci + bpdi;
    AR[SKW(ob+1)] = t1r*w1r - t1i*w1i;   AI[SKW(ob+1)] = t1r*w1i + t1i*w1r;
    AR[SKW(ob+2)] = s2r*w2r - s2i*w2i;   AI[SKW(ob+2)] = s2r*w2i + s2i*w2r;
    AR[SKW(ob+3)] = t3r*w3r - t3i*w3i;   AI[SKW(ob+3)] = t3r*w3i + t3i*w3r;
}

// ---------------- forward FFT: one frame per block (unchanged, passing) ----------------
__global__ void __launch_bounds__(256) fwd_kernel(int layer) {
    __shared__ float AR[SSZ], AI[SSZ], BR[SSZ], BI[SSZ];
    __shared__ float2 tws[256];
    int blk = blockIdx.x, bc = blk >> 7, f = blk & (FR-1), tid = threadIdx.x;
    { float sn, cs; sincospif(-(float)tid * (1.0f/512.0f), &sn, &cs); tws[tid] = make_float2(cs, sn); }
    const float* src = g_ident[layer] ? g_x[layer] : g_xm;
    const float2* xin2 = (const float2*)(src + (size_t)bc*NT);
    int ibase = f * (HOP/2);
    float zr[4], zi[4];
    #pragma unroll
    for (int u = 0; u < 4; u++) {
        int n = tid + u*256, gi = ibase + n;
        float2 v = (gi < NT/2) ? xin2[gi] : make_float2(0.f, 0.f);
        float he = 0.5f - 0.5f*cospif((float)n * (1.0f/512.0f));            // hann[2n]
        float ho = 0.5f - 0.5f*cospif((float)(2*n+1) * (1.0f/1024.0f));     // hann[2n+1]
        zr[u] = v.x * he;
        zi[u] = v.y * ho;
    }
    stage0_reg(zr, zi, AR, AI, tws, tid, false);
    __syncthreads();
    stages14(AR, AI, BR, BI, tws, tid, false);      // result in AR/AI
    float2* out = g_spec + (size_t)(bc*FR + f)*KB;
    for (int k = tid; k < KB; k += 256) {
        int ka = k & (NH-1), kb = (NH - k) & (NH-1);
        float xr = AR[SKW(ka)], xi = AI[SKW(ka)];
        float yr = AR[SKW(kb)], yi = -AI[SKW(kb)];
        float er  = 0.5f*(xr+yr), ei  = 0.5f*(xi+yi);
        float orr = 0.5f*(xr-yr), oii = 0.5f*(xi-yi);
        float sn, cs; sincospif(-(float)k * (1.0f/1024.0f), &sn, &cs);
        float wor = cs*orr - sn*oii, woi = cs*oii + sn*orr;
        out[k] = make_float2(er + woi, ei - wor);
    }
}

// ---------------- chunk-boundary carries for the frame recurrence ----------------
__global__ void carry_kernel(int layer) {
    int idx = blockIdx.x * 256 + threadIdx.x;
    if (idx >= BC*KB) return;
    int bc = idx / KB, k = idx - bc*KB;
    int c = bc & (NC-1);
    float T = g_T[(size_t)(layer*NC + c)*KB + k];
    float2 cr = make_float2(0.f, 0.f);
    const float2* base = g_spec + (size_t)bc*FR*KB + k;
    for (int f = 0; f < FR - FPC; f++) {
        float2 v = base[(size_t)f*KB];
        cr.x = (v.x + cr.x) * T;
        cr.y = (v.y + cr.y) * T;
        if (((f+1) & (FPC-1)) == 0)
            g_carry[(size_t)((f+1)/FPC)*BC*KB + idx] = cr;
    }
}

// ---------------- inverse radix-4 stage, register twiddle (w already e^{+2pi i j/1024}) ----------------
__device__ __forceinline__ void inv_stage(const float* sR, const float* sI, float* dR, float* dI,
                                          int lt, int m, int l2m, float wr, float wi) {
    float ar = sR[SKW(lt)],     ai = sI[SKW(lt)];
    float br = sR[SKW(lt+256)], bi = sI[SKW(lt+256)];
    float cr = sR[SKW(lt+512)], ci = sI[SKW(lt+512)];
    float dr = sR[SKW(lt+768)], di = sI[SKW(lt+768)];
    float apcr = ar+cr, apci = ai+ci, amcr = ar-cr, amci = ai-ci;
    float bpdr = br+dr, bpdi = bi+di, bmdr = br-dr, bmdi = bi-di;
    float t1r = amcr - bmdi, t1i = amci + bmdr;
    float t3r = amcr + bmdi, t3i = amci - bmdr;
    float w2r = wr*wr - wi*wi, w2i = 2.0f*wr*wi;
    float w3r = w2r*wr - w2i*wi, w3i = w2r*wi + w2i*wr;
    int q  = lt & (m-1);
    int ob = q + ((lt >> l2m) << (l2m + 2));
    float s2r = apcr - bpdr, s2i = apci - bpdi;
    dR[SKW(ob)]      = apcr + bpdr;       dI[SKW(ob)]      = apci + bpdi;
    dR[SKW(ob+m)]    = t1r*wr - t1i*wi;   dI[SKW(ob+m)]    = t1r*wi + t1i*wr;
    dR[SKW(ob+2*m)]  = s2r*w2r - s2i*w2i; dI[SKW(ob+2*m)]  = s2r*w2i + s2i*w2r;
    dR[SKW(ob+3*m)]  = t3r*w3r - t3i*w3i; dI[SKW(ob+3*m)]  = t3r*w3i + t3i*w3r;
}

// ---------------- sweep: per (bc, chunk): scan + inverse FFT + window + OA + tanh ----------------
// All tables in registers; last FFT stage fused into windowing (no smem round trip).
__global__ void __launch_bounds__(256) sweep_kernel(int layer, const float* __restrict__ gains) {
    extern __shared__ float sm[];
    float2* X  = (float2*)sm;            // [KB] post-scan spectrum (mirror source)
    float*  AR = (float*)(X + KB);
    float*  AI = AR + SSZ;
    float*  BR = AI + SSZ;
    float*  BI = BR + SSZ;
    float*  prevsec = BI + SSZ;          // [2][1024]

    int blk = blockIdx.x;
    int bc = blk >> 4, ch = blk & (CH-1);
    int lt = threadIdx.x;
    int c = bc & (NC-1);
    float gain = gains[layer*NC + c];

    // ---- frame-invariant per-thread constants ----
    float s0r, s0i;                       // e^{+2pi i lt/1024} = (cos, sin)(pi*lt/512); also hann-even base
    sincospif((float)lt * (1.0f/512.0f), &s0i, &s0r);
    float w1r_, w1i_, w2r_, w2i_, w3r_, w3i_;
    { float sn, cs;
      sincospif((float)(lt & ~3)  * (1.0f/512.0f), &sn, &cs); w1r_ = cs; w1i_ = sn;
      sincospif((float)(lt & ~15) * (1.0f/512.0f), &sn, &cs); w2r_ = cs; w2i_ = sn;
      sincospif((float)(lt & ~63) * (1.0f/512.0f), &sn, &cs); w3r_ = cs; w3i_ = sn; }
    float Wr, Wi;                         // e^{+i pi lt/1024}
    { float sn, cs; sincospif((float)lt * (1.0f/1024.0f), &sn, &cs); Wr = cs; Wi = sn; }
    float co_, so_;                       // hann-odd base
    { float sn, cs; sincospif((float)(2*lt+1) * (1.0f/1024.0f), &sn, &cs); co_ = cs; so_ = sn; }
    const float sc = 1.0f/(float)NH;
    float he[4], ho[4];                   // hann*scale at n = lt+256u (even/odd sample)
    he[0] = (0.5f - 0.5f*s0r)*sc; he[1] = (0.5f + 0.5f*s0i)*sc;
    he[2] = (0.5f + 0.5f*s0r)*sc; he[3] = (0.5f - 0.5f*s0i)*sc;
    ho[0] = (0.5f - 0.5f*co_)*sc; ho[1] = (0.5f + 0.5f*so_)*sc;
    ho[2] = (0.5f + 0.5f*co_)*sc; ho[3] = (0.5f - 0.5f*so_)*sc;
    // repack rotation: e^{+i pi k/1024} for k = lt+256u  =  W * e^{+i pi u/4}
    const float RC = 0.70710678118654752f;
    float csu[4], snu[4];
    csu[0] = Wr;            snu[0] = Wi;
    csu[1] = RC*(Wr - Wi);  snu[1] = RC*(Wr + Wi);
    csu[2] = -Wi;           snu[2] = Wr;
    csu[3] = -snu[1];       snu[3] = csu[1];

    // scan registers
    float Treg[5]; float2 creg[5];
    #pragma unroll
    for (int u = 0; u < 5; u++) {
        int k = lt + u*256;
        if (k < KB) {
            Treg[u] = g_T[(size_t)(layer*NC + c)*KB + k];
            creg[u] = ch ? g_carry[(size_t)ch*BC*KB + (size_t)bc*KB + k] : make_float2(0.f, 0.f);
        }
    }

    const float2* specb = g_spec + (size_t)bc*FR*KB + (size_t)(ch*FPC)*KB;
    float* xout = g_x[layer+1] + (size_t)bc*NT;

    // prefetch first frame
    float2 rv[5];
    #pragma unroll
    for (int u = 0; u < 5; u++) {
        int k = lt + u*256;
        if (k < KB) rv[u] = specb[k];
    }

    for (int fi = 0; fi < FPC; fi++) {
        int f = ch*FPC + fi;
        // scan update into X (own values stay in creg)
        #pragma unroll
        for (int u = 0; u < 5; u++) {
            int k = lt + u*256;
            if (k < KB) {
                creg[u].x = (rv[u].x + creg[u].x) * Treg[u];
                creg[u].y = (rv[u].y + creg[u].y) * Treg[u];
                X[k] = creg[u];
            }
        }
        __syncthreads();
        // prefetch next frame (latency hidden behind FFT)
        if (fi + 1 < FPC) {
            const float2* sp = specb + (size_t)(fi+1)*KB;
            #pragma unroll
            for (int u = 0; u < 5; u++) {
                int k = lt + u*256;
                if (k < KB) rv[u] = sp[k];
            }
        }
        // repack (own from regs, mirror from smem) fused with inverse stage 0
        {
            float zr[4], zi[4];
            #pragma unroll
            for (int u = 0; u < 4; u++) {
                float2 Xa = creg[u];
                float2 Yc = X[NH - (lt + u*256)];
                float yr = Yc.x, yi = -Yc.y;
                float er  = 0.5f*(Xa.x+yr), ei  = 0.5f*(Xa.y+yi);
                float orr = 0.5f*(Xa.x-yr), oii = 0.5f*(Xa.y-yi);
                float wor = csu[u]*orr - snu[u]*oii, woi = csu[u]*oii + snu[u]*orr;
                zr[u] = er - woi;
                zi[u] = ei + wor;
            }
            // stage 0 (inverse) with register twiddle s0
            float apcr = zr[0]+zr[2], apci = zi[0]+zi[2], amcr = zr[0]-zr[2], amci = zi[0]-zi[2];
            float bpdr = zr[1]+zr[3], bpdi = zi[1]+zi[3], bmdr = zr[1]-zr[3], bmdi = zi[1]-zi[3];
            float t1r = amcr - bmdi, t1i = amci + bmdr;
            float t3r = amcr + bmdi, t3i = amci - bmdr;
            float w2r = s0r*s0r - s0i*s0i, w2i = 2.0f*s0r*s0i;
            float w3r = w2r*s0r - w2i*s0i, w3i = w2r*s0i + w2i*s0r;
            float s2r = apcr - bpdr, s2i = apci - bpdi;
            int ob = 4*lt;
            AR[SKW(ob)]   = apcr + bpdr;           AI[SKW(ob)]   = apci + bpdi;
            AR[SKW(ob+1)] = t1r*s0r - t1i*s0i;     AI[SKW(ob+1)] = t1r*s0i + t1i*s0r;
            AR[SKW(ob+2)] = s2r*w2r - s2i*w2i;     AI[SKW(ob+2)] = s2r*w2i + s2i*w2r;
            AR[SKW(ob+3)] = t3r*w3r - t3i*w3i;     AI[SKW(ob+3)] = t3r*w3i + t3i*w3r;
        }
        __syncthreads();
        inv_stage(AR, AI, BR, BI, lt,  4, 2, w1r_, w1i_);   // s=1
        __syncthreads();
        inv_stage(BR, BI, AR, AI, lt, 16, 4, w2r_, w2i_);   // s=2
        __syncthreads();
        inv_stage(AR, AI, BR, BI, lt, 64, 6, w3r_, w3i_);   // s=3
        __syncthreads();
        // stage 4 (m=256, w=1): outputs land at n = lt+256u — keep in registers
        float y0r, y0i, y1r, y1i, y2r, y2i, y3r, y3i;
        {
            float ar = BR[SKW(lt)],     ai = BI[SKW(lt)];
            float br = BR[SKW(lt+256)], bi = BI[SKW(lt+256)];
            float cr = BR[SKW(lt+512)], ci = BI[SKW(lt+512)];
            float dr = BR[SKW(lt+768)], di = BI[SKW(lt+768)];
            float apcr = ar+cr, apci = ai+ci, amcr = ar-cr, amci = ai-ci;
            float bpdr = br+dr, bpdi = bi+di, bmdr = br-dr, bmdi = bi-di;
            y0r = apcr + bpdr; y0i = apci + bpdi;
            y1r = amcr - bmdi; y1i = amci + bmdr;
            y2r = apcr - bpdr; y2i = apci - bpdi;
            y3r = amcr + bmdi; y3i = amci - bmdr;
        }
        float ve[4] = { y0r*he[0], y1r*he[1], y2r*he[2], y3r*he[3] };
        float vo[4] = { y0i*ho[0], y1i*ho[1], y2i*ho[2], y3i*ho[3] };
        // in-block overlap-add + tanh
        float* rd = prevsec + (fi & 1)*1024;
        float* wr = prevsec + ((fi+1) & 1)*1024;
        if (fi > 0) {
            float2* out2 = (float2*)xout + (size_t)f*512;
            #pragma unroll
            for (int u = 0; u < 2; u++) {
                int n = lt + u*256;
                float a0 = rd[2*n]   + ve[u];
                float a1 = rd[2*n+1] + vo[u];
                out2[n] = make_float2(tanhf(gain*a0), tanhf(gain*a1));
            }
        } else {
            float2* bf = g_bnd_first + (size_t)(bc*CH + ch)*512;
            #pragma unroll
            for (int u = 0; u < 2; u++) {
                int n = lt + u*256;
                bf[n] = make_float2(ve[u], vo[u]);
            }
        }
        #pragma unroll
        for (int u = 2; u < 4; u++) {
            int n = lt + u*256;
            int j2 = 2*(n - 512);
            wr[j2]   = ve[u];
            wr[j2+1] = vo[u];
        }
        if (fi == FPC-1) {
            float2* bs = g_bnd_sec + (size_t)(bc*CH + ch)*512;
            #pragma unroll
            for (int u = 2; u < 4; u++) {
                int n = lt + u*256;
                bs[n - 512] = make_float2(ve[u], vo[u]);
            }
        }
        __syncthreads();
    }
}

// ---------------- stitch: chunk-boundary segments ----------------
__global__ void stitch_kernel(int layer, const float* __restrict__ gains) {
    int idx = blockIdx.x * 256 + threadIdx.x;       // float2 index over BC*CH*512
    if (idx >= BC*CH*512) return;
    int bc = idx / (CH*512);
    int r  = idx - bc*(CH*512);
    int ch = r >> 9, m = r & 511;
    int c = bc & (NC-1);
    float g = gains[layer*NC + c];
    float2 fv = g_bnd_first[idx];
    float2 sv = make_float2(0.f, 0.f);
    if (ch > 0) sv = g_bnd_sec[(size_t)(bc*CH + ch - 1)*512 + m];
    float2 o = make_float2(tanhf(g*(fv.x + sv.x)), tanhf(g*(fv.y + sv.y)));
    ((float2*)(g_x[layer+1] + (size_t)bc*NT))[(size_t)ch*FPC*512 + m] = o;
}

// ---------------- softmax layer mix + channel sum (float4) ----------------
__global__ void final_kernel(const float* __restrict__ mixer, float* __restrict__ out) {
    int idx = blockIdx.x * 256 + threadIdx.x;
    if (idx >= NB*NT/4) return;
    int b = idx / (NT/4), t4 = idx - b*(NT/4);
    float m0 = mixer[0], m1 = mixer[1], m2 = mixer[2], m3 = mixer[3];
    float mx = fmaxf(fmaxf(m0, m1), fmaxf(m2, m3));
    float e0 = expf(m0-mx), e1 = expf(m1-mx), e2 = expf(m2-mx), e3 = expf(m3-mx);
    float inv = 1.0f / (e0+e1+e2+e3);
    float w[4] = {e0*inv, e1*inv, e2*inv, e3*inv};
    float4 acc = make_float4(0.f,0.f,0.f,0.f);
    for (int c = 0; c < NC; c++) {
        size_t off4 = (size_t)(b*NC + c)*(NT/4) + t4;
        #pragma unroll
        for (int l = 0; l < 4; l++) {
            float4 v = ((const float4*)g_x[l])[off4];
            acc.x += w[l]*v.x; acc.y += w[l]*v.y; acc.z += w[l]*v.z; acc.w += w[l]*v.w;
        }
    }
    ((float4*)out)[idx] = acc;
}

// ---------------- sig passthrough ----------------
__global__ void copy_sig_kernel(const float* __restrict__ sig, float* __restrict__ out) {
    int i = blockIdx.x * 256 + threadIdx.x;
    if (i < NB*NC*NFR) out[NB*NT + i] = sig[i];
}

// ---------------- launch ----------------
extern "C" void kernel_launch(void* const* d_in, const int* in_sizes, int n_in,
                              void* d_out, int out_size) {
    const float* sig        = (const float*)d_in[0];
    const float* noise      = (const float*)d_in[1];
    const float* decays     = (const float*)d_in[2];
    const float* mixer      = (const float*)d_in[3];
    const float* transfers  = (const float*)d_in[4];
    const float* mixer_mats = (const float*)d_in[5];
    const float* gains      = (const float*)d_in[6];
    const float* fb         = (const float*)d_in[7];
    float* out = (float*)d_out;

    cudaFuncSetAttribute(sweep_kernel, cudaFuncAttributeMaxDynamicSharedMemorySize, SWEEP_BYTES);

    init_kernel<<<64, 256>>>(decays);
    ident_kernel<<<NL, 256>>>(mixer_mats);
    tmat_kernel<<<NL*NC, 256>>>(transfers, fb);
    x0_kernel<<<(BC*NT/4 + 255)/256, 256>>>(sig, noise);

    for (int l = 0; l < NL; l++) {
        dim3 mg(NT/256, NB);
        mix_kernel<<<mg, 256>>>(l, mixer_mats + l*NC*NC);   // early-exits when identity
        fwd_kernel<<<BC*FR, 256>>>(l);
        carry_kernel<<<(BC*KB + 255)/256, 256>>>(l);
        sweep_kernel<<<BC*CH, 256, SWEEP_BYTES>>>(l, gains);
        stitch_kernel<<<(BC*CH*512 + 255)/256, 256>>>(l, gains);
    }

    final_kernel<<<(NB*NT/4 + 255)/256, 256>>>(mixer, out);
    if (out_size >= NB*NT + NB*NC*NFR)
        copy_sig_kernel<<<(NB*NC*NFR + 255)/256, 256>>>(sig, out);
}

// round 14
// speedup vs baseline: 5.9943x; 1.1168x over previous
#include <cuda_runtime.h>
#include <math.h>

// ---------------- problem constants ----------------
#define NB 4            // batch
#define NC 32           // channels
#define NT 131072       // samples
#define NFR 256         // sig frames
#define SPF 512         // samples per sig frame
#define WS 2048         // window size
#define HOP 1024        // step
#define FR 128          // fft frames per signal
#define KB 1025         // rfft bins
#define BC (NB*NC)      // 128
#define NL 3            // layers
#define NH 1024         // complex FFT length (real 2048 packed)
#define CH 16           // chunks per signal
#define FPC 8           // frames per chunk

// skewed smem indexing: conflict-free for stride-4m scatter stores
#define SKW(i) ((i) + ((i) >> 5))
#define SSZ (NH + (NH >> 5) + 1)   // 1057

// sweep kernel dynamic smem (floats): float2 X[KB]; float AR,AI,BR,BI[SSZ]; prevsec[2][1024]
#define SWEEP_FLOATS (2*KB + 4*SSZ + 2048)
#define SWEEP_BYTES (SWEEP_FLOATS * 4)

// ---------------- device scratch (static: no runtime allocation) ----------------
__device__ float  g_env[NC*SPF];
__device__ float  g_T[NL*NC*KB];
__device__ float  g_x[NL+1][BC*NT];
__device__ float  g_xm[BC*NT];
__device__ float2 g_spec[BC*FR*KB];          // spectra
__device__ float2 g_carry[CH*BC*KB];         // chunk-entry carries (ch=0 unused)
__device__ float2 g_bnd_first[BC*CH*512];    // chunk-first-frame first half (pairs)
__device__ float2 g_bnd_sec[BC*CH*512];      // chunk-last-frame second half (pairs)
__device__ int    g_ident[NL];

// ---------------- init: envelopes ----------------
__global__ void init_kernel(const float* __restrict__ decays) {
    int tid = blockIdx.x * blockDim.x + threadIdx.x;
    if (tid < NC*SPF) {
        int ch = tid / SPF, j = tid - ch*SPF;
        float base = (float)(SPF-1 - j) * (1.0f/(float)(SPF-1));
        g_env[tid] = powf(base, decays[ch]);
    }
}

// ---------------- identity check for mixer matrices ----------------
__global__ void ident_kernel(const float* __restrict__ M) {
    __shared__ int ok;
    if (threadIdx.x == 0) ok = 1;
    __syncthreads();
    const float* m = M + blockIdx.x * NC*NC;
    for (int i = threadIdx.x; i < NC*NC; i += 256) {
        float expect = ((i / NC) == (i % NC)) ? 1.0f : 0.0f;
        if (m[i] != expect) atomicExch(&ok, 0);
    }
    __syncthreads();
    if (threadIdx.x == 0) g_ident[blockIdx.x] = ok;
}

// ---------------- T = transfers @ filter_bank (exploit ~1% sparsity) ----------------
__global__ void tmat_kernel(const float* __restrict__ transfers, const float* __restrict__ fb) {
    int lc  = blockIdx.x;
    int tid = threadIdx.x;
    const float* tr = transfers + (size_t)lc * KB;
    float acc[5] = {0.f,0.f,0.f,0.f,0.f};
    for (int j = 0; j < KB; j++) {
        float t = tr[j];
        if (t != 0.0f) {
            const float* row = fb + (size_t)j * KB;
            #pragma unroll
            for (int u = 0; u < 5; u++) {
                int k = tid + u*256;
                if (k < KB) acc[u] += t * row[k];
            }
        }
    }
    #pragma unroll
    for (int u = 0; u < 5; u++) {
        int k = tid + u*256;
        if (k < KB) g_T[(size_t)lc*KB + k] = acc[u];
    }
}

// ---------------- excitation (float4) ----------------
__global__ void x0_kernel(const float* __restrict__ sig, const float* __restrict__ noise) {
    int idx = blockIdx.x * 256 + threadIdx.x;       // float4 index
    if (idx >= BC*NT/4) return;
    int bc = idx / (NT/4), t4 = idx - bc*(NT/4);
    int t  = t4 * 4;
    int c = bc & (NC-1);
    int f = t >> 9, j = t & 511;
    float s = sig[bc*NFR + f];
    float4 nz = ((const float4*)noise)[t4];
    float4 ev = ((const float4*)g_env)[c*(SPF/4) + (j >> 2)];
    float4 o;
    o.x = s * ev.x * nz.x;  o.y = s * ev.y * nz.y;
    o.z = s * ev.z * nz.z;  o.w = s * ev.w * nz.w;
    ((float4*)(g_x[0] + (size_t)bc*NT))[t4] = o;
}

// ---------------- channel mixing (only runs when mixer_mat != identity) ----------------
__global__ void __launch_bounds__(256) mix_kernel(int layer, const float* __restrict__ M) {
    if (g_ident[layer]) return;
    __shared__ float Ms[NC*NC];
    int b = blockIdx.y, t = blockIdx.x * 256 + threadIdx.x;
    for (int i = threadIdx.x; i < NC*NC; i += 256) Ms[i] = M[i];
    __syncthreads();
    const float* xin = g_x[layer] + (size_t)b*NC*NT + t;
    float xv[NC];
    #pragma unroll
    for (int c = 0; c < NC; c++) xv[c] = xin[(size_t)c*NT];
    float* xo = g_xm + (size_t)b*NC*NT + t;
    #pragma unroll
    for (int d = 0; d < NC; d++) {
        float s = 0.f;
        #pragma unroll
        for (int c = 0; c < NC; c++) s += xv[c] * Ms[c*NC + d];
        xo[(size_t)d*NT] = s;
    }
}

// ---------------- forward radix-4 stage, register twiddle (w = e^{-2pi i j/1024}) ----------------
__device__ __forceinline__ void fwd_stage(const float* sR, const float* sI, float* dR, float* dI,
                                          int lt, int m, int l2m, float wr, float wi) {
    float ar = sR[SKW(lt)],     ai = sI[SKW(lt)];
    float br = sR[SKW(lt+256)], bi = sI[SKW(lt+256)];
    float cr = sR[SKW(lt+512)], ci = sI[SKW(lt+512)];
    float dr = sR[SKW(lt+768)], di = sI[SKW(lt+768)];
    float apcr = ar+cr, apci = ai+ci, amcr = ar-cr, amci = ai-ci;
    float bpdr = br+dr, bpdi = bi+di, bmdr = br-dr, bmdi = bi-di;
    float t1r = amcr + bmdi, t1i = amci - bmdr;
    float t3r = amcr - bmdi, t3i = amci + bmdr;
    float w2r = wr*wr - wi*wi, w2i = 2.0f*wr*wi;
    float w3r = w2r*wr - w2i*wi, w3i = w2r*wi + w2i*wr;
    int q  = lt & (m-1);
    int ob = q + ((lt >> l2m) << (l2m + 2));
    float s2r = apcr - bpdr, s2i = apci - bpdi;
    dR[SKW(ob)]      = apcr + bpdr;       dI[SKW(ob)]      = apci + bpdi;
    dR[SKW(ob+m)]    = t1r*wr - t1i*wi;   dI[SKW(ob+m)]    = t1r*wi + t1i*wr;
    dR[SKW(ob+2*m)]  = s2r*w2r - s2i*w2i; dI[SKW(ob+2*m)]  = s2r*w2i + s2i*w2r;
    dR[SKW(ob+3*m)]  = t3r*w3r - t3i*w3i; dI[SKW(ob+3*m)]  = t3r*w3i + t3i*w3r;
}

// ---------------- forward FFT: one frame per block, all-register twiddles ----------------
__global__ void __launch_bounds__(256) fwd_kernel(int layer) {
    __shared__ float AR[SSZ], AI[SSZ], BR[SSZ], BI[SSZ];
    int blk = blockIdx.x, bc = blk >> 7, f = blk & (FR-1), lt = threadIdx.x;

    // ---- frame-invariant per-thread constants ----
    float cs_, sn_;                        // (cos,sin)(pi lt/512)
    sincospif((float)lt * (1.0f/512.0f), &sn_, &cs_);
    float s0r = cs_, s0i = -sn_;           // stage0 twiddle e^{-2pi i lt/1024}
    float w1r_, w1i_, w2r_, w2i_, w3r_, w3i_;
    { float sn, cs;
      sincospif(-(float)(lt & ~3)  * (1.0f/512.0f), &sn, &cs); w1r_ = cs; w1i_ = sn;
      sincospif(-(float)(lt & ~15) * (1.0f/512.0f), &sn, &cs); w2r_ = cs; w2i_ = sn;
      sincospif(-(float)(lt & ~63) * (1.0f/512.0f), &sn, &cs); w3r_ = cs; w3i_ = sn; }
    float he[4], ho[4];                    // hann at samples 2n / 2n+1, n = lt+256u
    he[0] = 0.5f - 0.5f*cs_; he[1] = 0.5f + 0.5f*sn_;
    he[2] = 0.5f + 0.5f*cs_; he[3] = 0.5f - 0.5f*sn_;
    { float sn, cs; sincospif((float)(2*lt+1) * (1.0f/1024.0f), &sn, &cs);
      ho[0] = 0.5f - 0.5f*cs; ho[1] = 0.5f + 0.5f*sn;
      ho[2] = 0.5f + 0.5f*cs; ho[3] = 0.5f - 0.5f*sn; }
    // unpack rotation e^{-i pi k/1024}, k = lt+256u: V * e^{-i pi u/4}
    const float RC = 0.70710678118654752f;
    float Vr, Vi;
    { float sn, cs; sincospif((float)lt * (1.0f/1024.0f), &sn, &cs); Vr = cs; Vi = -sn; }
    float ucs[4], usn[4];
    ucs[0] = Vr;            usn[0] = Vi;
    ucs[1] = RC*(Vr + Vi);  usn[1] = RC*(Vi - Vr);
    ucs[2] = Vi;            usn[2] = -Vr;
    ucs[3] = usn[1];        usn[3] = -ucs[1];

    // ---- window + pack + stage 0 from global ----
    const float* src = g_ident[layer] ? g_x[layer] : g_xm;
    const float2* xin2 = (const float2*)(src + (size_t)bc*NT);
    int ibase = f * (HOP/2);
    float zr[4], zi[4];
    #pragma unroll
    for (int u = 0; u < 4; u++) {
        int n = lt + u*256, gi = ibase + n;
        float2 v = (gi < NT/2) ? xin2[gi] : make_float2(0.f, 0.f);
        zr[u] = v.x * he[u];
        zi[u] = v.y * ho[u];
    }
    {
        float apcr = zr[0]+zr[2], apci = zi[0]+zi[2], amcr = zr[0]-zr[2], amci = zi[0]-zi[2];
        float bpdr = zr[1]+zr[3], bpdi = zi[1]+zi[3], bmdr = zr[1]-zr[3], bmdi = zi[1]-zi[3];
        float t1r = amcr + bmdi, t1i = amci - bmdr;
        float t3r = amcr - bmdi, t3i = amci + bmdr;
        float w2r = s0r*s0r - s0i*s0i, w2i = 2.0f*s0r*s0i;
        float w3r = w2r*s0r - w2i*s0i, w3i = w2r*s0i + w2i*s0r;
        float s2r = apcr - bpdr, s2i = apci - bpdi;
        int ob = 4*lt;
        AR[SKW(ob)]   = apcr + bpdr;         AI[SKW(ob)]   = apci + bpdi;
        AR[SKW(ob+1)] = t1r*s0r - t1i*s0i;   AI[SKW(ob+1)] = t1r*s0i + t1i*s0r;
        AR[SKW(ob+2)] = s2r*w2r - s2i*w2i;   AI[SKW(ob+2)] = s2r*w2i + s2i*w2r;
        AR[SKW(ob+3)] = t3r*w3r - t3i*w3i;   AI[SKW(ob+3)] = t3r*w3i + t3i*w3r;
    }
    __syncthreads();
    fwd_stage(AR, AI, BR, BI, lt,  4, 2, w1r_, w1i_);   // s=1
    __syncthreads();
    fwd_stage(BR, BI, AR, AI, lt, 16, 4, w2r_, w2i_);   // s=2
    __syncthreads();
    fwd_stage(AR, AI, BR, BI, lt, 64, 6, w3r_, w3i_);   // s=3
    __syncthreads();
    {   // stage 4: m=256, twiddle = 1, natural order out (ob = lt)
        float ar = BR[SKW(lt)],     ai = BI[SKW(lt)];
        float br = BR[SKW(lt+256)], bi = BI[SKW(lt+256)];
        float cr = BR[SKW(lt+512)], ci = BI[SKW(lt+512)];
        float dr = BR[SKW(lt+768)], di = BI[SKW(lt+768)];
        float apcr = ar+cr, apci = ai+ci, amcr = ar-cr, amci = ai-ci;
        float bpdr = br+dr, bpdi = bi+di, bmdr = br-dr, bmdi = bi-di;
        AR[SKW(lt)]     = apcr + bpdr;  AI[SKW(lt)]     = apci + bpdi;
        AR[SKW(lt+256)] = amcr + bmdi;  AI[SKW(lt+256)] = amci - bmdr;
        AR[SKW(lt+512)] = apcr - bpdr;  AI[SKW(lt+512)] = apci - bpdi;
        AR[SKW(lt+768)] = amcr - bmdi;  AI[SKW(lt+768)] = amci + bmdr;
    }
    __syncthreads();
    // ---- Hermitian unpack with register twiddles ----
    float2* out = g_spec + (size_t)(bc*FR + f)*KB;
    #pragma unroll
    for (int u = 0; u < 4; u++) {
        int k = lt + u*256;
        int kb = (NH - k) & (NH-1);
        float xr = AR[SKW(k)],  xi = AI[SKW(k)];
        float yr = AR[SKW(kb)], yi = -AI[SKW(kb)];
        float er  = 0.5f*(xr+yr), ei  = 0.5f*(xi+yi);
        float orr = 0.5f*(xr-yr), oii = 0.5f*(xi-yi);
        float wor = ucs[u]*orr - usn[u]*oii, woi = ucs[u]*oii + usn[u]*orr;
        out[k] = make_float2(er + woi, ei - wor);
    }
    if (lt == 0) {
        // k = 1024: X = Re(Z[0]) - Im(Z[0])  (w = e^{-i pi} = -1)
        out[NH] = make_float2(AR[0] - AI[0], 0.f);
    }
}

// ---------------- chunk-boundary carries (MLP-8 batched loads) ----------------
__global__ void carry_kernel(int layer) {
    int idx = blockIdx.x * 256 + threadIdx.x;
    if (idx >= BC*KB) return;
    int bc = idx / KB, k = idx - bc*KB;
    int c = bc & (NC-1);
    float T = g_T[(size_t)(layer*NC + c)*KB + k];
    float2 cr = make_float2(0.f, 0.f);
    const float2* base = g_spec + (size_t)bc*FR*KB + k;
    for (int chb = 1; chb < CH; chb++) {
        float2 v[FPC];
        #pragma unroll
        for (int i = 0; i < FPC; i++)
            v[i] = base[(size_t)((chb-1)*FPC + i)*KB];
        #pragma unroll
        for (int i = 0; i < FPC; i++) {
            cr.x = (v[i].x + cr.x) * T;
            cr.y = (v[i].y + cr.y) * T;
        }
        g_carry[(size_t)chb*BC*KB + idx] = cr;
    }
}

// ---------------- inverse radix-4 stage, register twiddle (w = e^{+2pi i j/1024}) ----------------
__device__ __forceinline__ void inv_stage(const float* sR, const float* sI, float* dR, float* dI,
                                          int lt, int m, int l2m, float wr, float wi) {
    float ar = sR[SKW(lt)],     ai = sI[SKW(lt)];
    float br = sR[SKW(lt+256)], bi = sI[SKW(lt+256)];
    float cr = sR[SKW(lt+512)], ci = sI[SKW(lt+512)];
    float dr = sR[SKW(lt+768)], di = sI[SKW(lt+768)];
    float apcr = ar+cr, apci = ai+ci, amcr = ar-cr, amci = ai-ci;
    float bpdr = br+dr, bpdi = bi+di, bmdr = br-dr, bmdi = bi-di;
    float t1r = amcr - bmdi, t1i = amci + bmdr;
    float t3r = amcr + bmdi, t3i = amci - bmdr;
    float w2r = wr*wr - wi*wi, w2i = 2.0f*wr*wi;
    float w3r = w2r*wr - w2i*wi, w3i = w2r*wi + w2i*wr;
    int q  = lt & (m-1);
    int ob = q + ((lt >> l2m) << (l2m + 2));
    float s2r = apcr - bpdr, s2i = apci - bpdi;
    dR[SKW(ob)]      = apcr + bpdr;       dI[SKW(ob)]      = apci + bpdi;
    dR[SKW(ob+m)]    = t1r*wr - t1i*wi;   dI[SKW(ob+m)]    = t1r*wi + t1i*wr;
    dR[SKW(ob+2*m)]  = s2r*w2r - s2i*w2i; dI[SKW(ob+2*m)]  = s2r*w2i + s2i*w2r;
    dR[SKW(ob+3*m)]  = t3r*w3r - t3i*w3i; dI[SKW(ob+3*m)]  = t3r*w3i + t3i*w3r;
}

// ---------------- sweep: per (bc, chunk): scan + inverse FFT + window + OA + tanh ----------------
__global__ void __launch_bounds__(256) sweep_kernel(int layer, const float* __restrict__ gains) {
    extern __shared__ float sm[];
    float2* X  = (float2*)sm;            // [KB] post-scan spectrum (mirror source)
    float*  AR = (float*)(X + KB);
    float*  AI = AR + SSZ;
    float*  BR = AI + SSZ;
    float*  BI = BR + SSZ;
    float*  prevsec = BI + SSZ;          // [2][1024]

    int blk = blockIdx.x;
    int bc = blk >> 4, ch = blk & (CH-1);
    int lt = threadIdx.x;
    int c = bc & (NC-1);
    float gain = gains[layer*NC + c];

    // ---- frame-invariant per-thread constants ----
    float s0r, s0i;
    sincospif((float)lt * (1.0f/512.0f), &s0i, &s0r);
    float w1r_, w1i_, w2r_, w2i_, w3r_, w3i_;
    { float sn, cs;
      sincospif((float)(lt & ~3)  * (1.0f/512.0f), &sn, &cs); w1r_ = cs; w1i_ = sn;
      sincospif((float)(lt & ~15) * (1.0f/512.0f), &sn, &cs); w2r_ = cs; w2i_ = sn;
      sincospif((float)(lt & ~63) * (1.0f/512.0f), &sn, &cs); w3r_ = cs; w3i_ = sn; }
    float Wr, Wi;
    { float sn, cs; sincospif((float)lt * (1.0f/1024.0f), &sn, &cs); Wr = cs; Wi = sn; }
    float co_, so_;
    { float sn, cs; sincospif((float)(2*lt+1) * (1.0f/1024.0f), &sn, &cs); co_ = cs; so_ = sn; }
    const float sc = 1.0f/(float)NH;
    float he[4], ho[4];
    he[0] = (0.5f - 0.5f*s0r)*sc; he[1] = (0.5f + 0.5f*s0i)*sc;
    he[2] = (0.5f + 0.5f*s0r)*sc; he[3] = (0.5f - 0.5f*s0i)*sc;
    ho[0] = (0.5f - 0.5f*co_)*sc; ho[1] = (0.5f + 0.5f*so_)*sc;
    ho[2] = (0.5f + 0.5f*co_)*sc; ho[3] = (0.5f - 0.5f*so_)*sc;
    const float RC = 0.70710678118654752f;
    float csu[4], snu[4];
    csu[0] = Wr;            snu[0] = Wi;
    csu[1] = RC*(Wr - Wi);  snu[1] = RC*(Wr + Wi);
    csu[2] = -Wi;           snu[2] = Wr;
    csu[3] = -snu[1];       snu[3] = csu[1];

    // scan registers
    float Treg[5]; float2 creg[5];
    #pragma unroll
    for (int u = 0; u < 5; u++) {
        int k = lt + u*256;
        if (k < KB) {
            Treg[u] = g_T[(size_t)(layer*NC + c)*KB + k];
            creg[u] = ch ? g_carry[(size_t)ch*BC*KB + (size_t)bc*KB + k] : make_float2(0.f, 0.f);
        }
    }

    const float2* specb = g_spec + (size_t)bc*FR*KB + (size_t)(ch*FPC)*KB;
    float* xout = g_x[layer+1] + (size_t)bc*NT;

    // prefetch first frame
    float2 rv[5];
    #pragma unroll
    for (int u = 0; u < 5; u++) {
        int k = lt + u*256;
        if (k < KB) rv[u] = specb[k];
    }

    for (int fi = 0; fi < FPC; fi++) {
        int f = ch*FPC + fi;
        #pragma unroll
        for (int u = 0; u < 5; u++) {
            int k = lt + u*256;
            if (k < KB) {
                creg[u].x = (rv[u].x + creg[u].x) * Treg[u];
                creg[u].y = (rv[u].y + creg[u].y) * Treg[u];
                X[k] = creg[u];
            }
        }
        __syncthreads();
        if (fi + 1 < FPC) {
            const float2* sp = specb + (size_t)(fi+1)*KB;
            #pragma unroll
            for (int u = 0; u < 5; u++) {
                int k = lt + u*256;
                if (k < KB) rv[u] = sp[k];
            }
        }
        {
            float zr[4], zi[4];
            #pragma unroll
            for (int u = 0; u < 4; u++) {
                float2 Xa = creg[u];
                float2 Yc = X[NH - (lt + u*256)];
                float yr = Yc.x, yi = -Yc.y;
                float er  = 0.5f*(Xa.x+yr), ei  = 0.5f*(Xa.y+yi);
                float orr = 0.5f*(Xa.x-yr), oii = 0.5f*(Xa.y-yi);
                float wor = csu[u]*orr - snu[u]*oii, woi = csu[u]*oii + snu[u]*orr;
                zr[u] = er - woi;
                zi[u] = ei + wor;
            }
            float apcr = zr[0]+zr[2], apci = zi[0]+zi[2], amcr = zr[0]-zr[2], amci = zi[0]-zi[2];
            float bpdr = zr[1]+zr[3], bpdi = zi[1]+zi[3], bmdr = zr[1]-zr[3], bmdi = zi[1]-zi[3];
            float t1r = amcr - bmdi, t1i = amci + bmdr;
            float t3r = amcr + bmdi, t3i = amci - bmdr;
            float w2r = s0r*s0r - s0i*s0i, w2i = 2.0f*s0r*s0i;
            float w3r = w2r*s0r - w2i*s0i, w3i = w2r*s0i + w2i*s0r;
            float s2r = apcr - bpdr, s2i = apci - bpdi;
            int ob = 4*lt;
            AR[SKW(ob)]   = apcr + bpdr;           AI[SKW(ob)]   = apci + bpdi;
            AR[SKW(ob+1)] = t1r*s0r - t1i*s0i;     AI[SKW(ob+1)] = t1r*s0i + t1i*s0r;
            AR[SKW(ob+2)] = s2r*w2r - s2i*w2i;     AI[SKW(ob+2)] = s2r*w2i + s2i*w2r;
            AR[SKW(ob+3)] = t3r*w3r - t3i*w3i;     AI[SKW(ob+3)] = t3r*w3i + t3i*w3r;
        }
        __syncthreads();
        inv_stage(AR, AI, BR, BI, lt,  4, 2, w1r_, w1i_);
        __syncthreads();
        inv_stage(BR, BI, AR, AI, lt, 16, 4, w2r_, w2i_);
        __syncthreads();
        inv_stage(AR, AI, BR, BI, lt, 64, 6, w3r_, w3i_);
        __syncthreads();
        float y0r, y0i, y1r, y1i, y2r, y2i, y3r, y3i;
        {
            float ar = BR[SKW(lt)],     ai = BI[SKW(lt)];
            float br = BR[SKW(lt+256)], bi = BI[SKW(lt+256)];
            float cr = BR[SKW(lt+512)], ci = BI[SKW(lt+512)];
            float dr = BR[SKW(lt+768)], di = BI[SKW(lt+768)];
            float apcr = ar+cr, apci = ai+ci, amcr = ar-cr, amci = ai-ci;
            float bpdr = br+dr, bpdi = bi+di, bmdr = br-dr, bmdi = bi-di;
            y0r = apcr + bpdr; y0i = apci + bpdi;
            y1r = amcr - bmdi; y1i = amci + bmdr;
            y2r = apcr - bpdr; y2i = apci - bpdi;
            y3r = amcr + bmdi; y3i = amci - bmdr;
        }
        float ve[4] = { y0r*he[0], y1r*he[1], y2r*he[2], y3r*he[3] };
        float vo[4] = { y0i*ho[0], y1i*ho[1], y2i*ho[2], y3i*ho[3] };
        float* rd = prevsec + (fi & 1)*1024;
        float* wr = prevsec + ((fi+1) & 1)*1024;
        if (fi > 0) {
            float2* out2 = (float2*)xout + (size_t)f*512;
            #pragma unroll
            for (int u = 0; u < 2; u++) {
                int n = lt + u*256;
                float a0 = rd[2*n]   + ve[u];
                float a1 = rd[2*n+1] + vo[u];
                out2[n] = make_float2(tanhf(gain*a0), tanhf(gain*a1));
            }
        } else {
            float2* bf = g_bnd_first + (size_t)(bc*CH + ch)*512;
            #pragma unroll
            for (int u = 0; u < 2; u++) {
                int n = lt + u*256;
                bf[n] = make_float2(ve[u], vo[u]);
            }
        }
        #pragma unroll
        for (int u = 2; u < 4; u++) {
            int n = lt + u*256;
            int j2 = 2*(n - 512);
            wr[j2]   = ve[u];
            wr[j2+1] = vo[u];
        }
        if (fi == FPC-1) {
            float2* bs = g_bnd_sec + (size_t)(bc*CH + ch)*512;
            #pragma unroll
            for (int u = 2; u < 4; u++) {
                int n = lt + u*256;
                bs[n - 512] = make_float2(ve[u], vo[u]);
            }
        }
        __syncthreads();
    }
}

// ---------------- stitch: chunk-boundary segments ----------------
__global__ void stitch_kernel(int layer, const float* __restrict__ gains) {
    int idx = blockIdx.x * 256 + threadIdx.x;       // float2 index over BC*CH*512
    if (idx >= BC*CH*512) return;
    int bc = idx / (CH*512);
    int r  = idx - bc*(CH*512);
    int ch = r >> 9, m = r & 511;
    int c = bc & (NC-1);
    float g = gains[layer*NC + c];
    float2 fv = g_bnd_first[idx];
    float2 sv = make_float2(0.f, 0.f);
    if (ch > 0) sv = g_bnd_sec[(size_t)(bc*CH + ch - 1)*512 + m];
    float2 o = make_float2(tanhf(g*(fv.x + sv.x)), tanhf(g*(fv.y + sv.y)));
    ((float2*)(g_x[layer+1] + (size_t)bc*NT))[(size_t)ch*FPC*512 + m] = o;
}

// ---------------- softmax layer mix + channel sum (float4) ----------------
__global__ void final_kernel(const float* __restrict__ mixer, float* __restrict__ out) {
    int idx = blockIdx.x * 256 + threadIdx.x;
    if (idx >= NB*NT/4) return;
    int b = idx / (NT/4), t4 = idx - b*(NT/4);
    float m0 = mixer[0], m1 = mixer[1], m2 = mixer[2], m3 = mixer[3];
    float mx = fmaxf(fmaxf(m0, m1), fmaxf(m2, m3));
    float e0 = expf(m0-mx), e1 = expf(m1-mx), e2 = expf(m2-mx), e3 = expf(m3-mx);
    float inv = 1.0f / (e0+e1+e2+e3);
    float w[4] = {e0*inv, e1*inv, e2*inv, e3*inv};
    float4 acc = make_float4(0.f,0.f,0.f,0.f);
    for (int c = 0; c < NC; c++) {
        size_t off4 = (size_t)(b*NC + c)*(NT/4) + t4;
        #pragma unroll
        for (int l = 0; l < 4; l++) {
            float4 v = ((const float4*)g_x[l])[off4];
            acc.x += w[l]*v.x; acc.y += w[l]*v.y; acc.z += w[l]*v.z; acc.w += w[l]*v.w;
        }
    }
    ((float4*)out)[idx] = acc;
}

// ---------------- sig passthrough ----------------
__global__ void copy_sig_kernel(const float* __restrict__ sig, float* __restrict__ out) {
    int i = blockIdx.x * 256 + threadIdx.x;
    if (i < NB*NC*NFR) out[NB*NT + i] = sig[i];
}

// ---------------- launch ----------------
extern "C" void kernel_launch(void* const* d_in, const int* in_sizes, int n_in,
                              void* d_out, int out_size) {
    const float* sig        = (const float*)d_in[0];
    const float* noise      = (const float*)d_in[1];
    const float* decays     = (const float*)d_in[2];
    const float* mixer      = (const float*)d_in[3];
    const float* transfers  = (const float*)d_in[4];
    const float* mixer_mats = (const float*)d_in[5];
    const float* gains      = (const float*)d_in[6];
    const float* fb         = (const float*)d_in[7];
    float* out = (float*)d_out;

    cudaFuncSetAttribute(sweep_kernel, cudaFuncAttributeMaxDynamicSharedMemorySize, SWEEP_BYTES);

    init_kernel<<<64, 256>>>(decays);
    ident_kernel<<<NL, 256>>>(mixer_mats);
    tmat_kernel<<<NL*NC, 256>>>(transfers, fb);
    x0_kernel<<<(BC*NT/4 + 255)/256, 256>>>(sig, noise);

    for (int l = 0; l < NL; l++) {
        dim3 mg(NT/256, NB);
        mix_kernel<<<mg, 256>>>(l, mixer_mats + l*NC*NC);   // early-exits when identity
        fwd_kernel<<<BC*FR, 256>>>(l);
        carry_kernel<<<(BC*KB + 255)/256, 256>>>(l);
        sweep_kernel<<<BC*CH, 256, SWEEP_BYTES>>>(l, gains);
        stitch_kernel<<<(BC*CH*512 + 255)/256, 256>>>(l, gains);
    }

    final_kernel<<<(NB*NT/4 + 255)/256, 256>>>(mixer, out);
    if (out_size >= NB*NT + NB*NC*NFR)
        copy_sig_kernel<<<(NB*NC*NFR + 255)/256, 256>>>(sig, out);
}